// round 15
// baseline (speedup 1.0000x reference)
#include <cuda_runtime.h>
#include <cuda_bf16.h>
#include <math.h>
#include <cstdint>

#define N_NODES 20000
#define K_REL   4
#define E_EDGES 320000
#define INDIM   1024
#define HINDIM  256
#define DDIM    128
#define GATEH   128
#define TEMP_INV (1.0f/0.6f)
#define MCLAMP  20.0f
#define NBUCKET (K_REL * N_NODES)
#define SSTRIDE 132

// ---------------- scratch ----------------
__device__ float g_buf0[N_NODES * HINDIM];
__device__ float g_buf1[N_NODES * HINDIM];
__device__ float g_H[N_NODES * DDIM];
__device__ float g_Z[N_NODES * DDIM];
__device__ float g_M[N_NODES * K_REL * DDIM];
__device__ float g_gateH[N_NODES * GATEH];
__device__ float g_scores[N_NODES * K_REL];
__device__ float g_Xres[N_NODES * DDIM];
__device__ __align__(16) float g_colsum[2 * SSTRIDE];
__device__ __align__(16) float g_stats[2 * SSTRIDE];
__device__ int   g_done[2];
// CSR
__device__ int g_cnt[NBUCKET];
__device__ int g_off[NBUCKET + 1];
__device__ int g_cur[NBUCKET];
__device__ int g_ecol[K_REL * E_EDGES];
__device__ int g_bsum[256];
__device__ int g_btop[256];

// ================= helpers =================
__device__ __forceinline__ uint32_t smem_u32(const void* p) {
    uint32_t a;
    asm("{ .reg .u64 t; cvta.to.shared.u64 t, %1; cvt.u32.u64 %0, t; }" : "=r"(a) : "l"(p));
    return a;
}
__device__ __forceinline__ void ldsm_x4(uint32_t* r, uint32_t addr) {
    asm volatile("ldmatrix.sync.aligned.m8n8.x4.shared.b16 {%0,%1,%2,%3}, [%4];"
        : "=r"(r[0]), "=r"(r[1]), "=r"(r[2]), "=r"(r[3]) : "r"(addr));
}
__device__ __forceinline__ void ldsm_x4_t(uint32_t* r, uint32_t addr) {
    asm volatile("ldmatrix.sync.aligned.m8n8.x4.trans.shared.b16 {%0,%1,%2,%3}, [%4];"
        : "=r"(r[0]), "=r"(r[1]), "=r"(r[2]), "=r"(r[3]) : "r"(addr));
}
__device__ __forceinline__ void mma_bf16(float* c, const uint32_t* a, const uint32_t* b) {
    asm volatile("mma.sync.aligned.m16n8k16.row.col.f32.bf16.bf16.f32 "
        "{%0,%1,%2,%3}, {%4,%5,%6,%7}, {%8,%9}, {%0,%1,%2,%3};"
        : "+f"(c[0]), "+f"(c[1]), "+f"(c[2]), "+f"(c[3])
        : "r"(a[0]), "r"(a[1]), "r"(a[2]), "r"(a[3]), "r"(b[0]), "r"(b[1]));
}
__device__ __forceinline__ uint32_t pack2(float a, float b) {
    __nv_bfloat162 h = __floats2bfloat162_rn(a, b);
    return *reinterpret_cast<uint32_t*>(&h);
}

// ================= generic bf16 3-split GEMM: BM=64, BN=128, 256 threads =================
#define GT 256
#define ROWB_A 80
#define ROWB_B 272
#define A_TILE (64 * ROWB_A)
#define B_TILE (32 * ROWB_B)
#define STAGE_B (2 * A_TILE + 2 * B_TILE)
#define GEMM_SMEM (2 * STAGE_B)
#define B_OFF (2 * A_TILE)

template <bool RELU, bool BIAS, bool DUAL, bool REDUCE, bool GHLD, bool ANORM>
__global__ __launch_bounds__(GT, 2) void mma_gemm(
    const float* __restrict__ A, const float* __restrict__ B1,
    const float* __restrict__ bias, float* __restrict__ C1,
    int M, int K, int N,
    const float* __restrict__ B2, float* __restrict__ C2,
    const float* __restrict__ gh, const float* __restrict__ ldg_,
    const float* __restrict__ wld, const float* __restrict__ rb1,
    const float* __restrict__ rb2, const float* __restrict__ rb3,
    const float* __restrict__ anorm_stats)
{
    extern __shared__ __align__(128) char smem[];
    const int tid = threadIdx.x;
    const int lane = tid & 31;
    const int wid = tid >> 5;
    const int warp_m = wid & 1;
    const int warp_n = wid >> 1;
    const int rowBase = blockIdx.y * 64;
    const int nch = K >> 5;

    const float* Bp = B1;
    float* Cp = C1;
    int cb = blockIdx.x * 128;
    if (DUAL) {
        if (blockIdx.x == 1) { Bp = B2; Cp = C2; }
        cb = 0;
    }

    float anorm_inv = 0.f;
    if (ANORM) anorm_inv = __ldg(anorm_stats + DDIM);

    float acc[2][4][4];
#pragma unroll
    for (int i = 0; i < 2; i++)
#pragma unroll
        for (int j = 0; j < 4; j++)
#pragma unroll
            for (int q = 0; q < 4; q++) acc[i][j][q] = 0.f;

    const uint32_t sb = smem_u32(smem);
    const int aRow = warp_m * 32 + (lane & 7) + ((lane >> 3) & 1) * 8;
    const int aK   = ((lane >> 4) & 1) * 8;
    const uint32_t aBase = sb + (uint32_t)(aRow * ROWB_A + aK * 2);
    const uint32_t bBase = sb + (uint32_t)B_OFF
                         + (uint32_t)((lane & 15) * ROWB_B + (lane >> 4) * 16);

    float4 aR[2], bR[4];

    auto gload = [&](int c) {
        const int k0 = c << 5;
#pragma unroll
        for (int j = 0; j < 2; j++) {
            int idx = tid + j * GT;
            int r = idx >> 3;
            int col = (idx & 7) * 4;
            int gr = rowBase + r;
            float4 v = make_float4(0.f, 0.f, 0.f, 0.f);
            if (gr < M) {
                v = *reinterpret_cast<const float4*>(A + (size_t)gr * K + k0 + col);
                if (ANORM) {
                    float4 mu = *reinterpret_cast<const float4*>(anorm_stats + k0 + col);
                    v.x = fmaxf((v.x - mu.x) * anorm_inv, 0.f);
                    v.y = fmaxf((v.y - mu.y) * anorm_inv, 0.f);
                    v.z = fmaxf((v.z - mu.z) * anorm_inv, 0.f);
                    v.w = fmaxf((v.w - mu.w) * anorm_inv, 0.f);
                }
            }
            aR[j] = v;
        }
#pragma unroll
        for (int j = 0; j < 4; j++) {
            int idx = tid + j * GT;
            int br = idx >> 5;
            int bcol = (idx & 31) * 4;
            bR[j] = *reinterpret_cast<const float4*>(Bp + (size_t)(k0 + br) * N + cb + bcol);
        }
    };
    auto sstore = [&](int s) {
        char* st = smem + s * STAGE_B;
#pragma unroll
        for (int j = 0; j < 2; j++) {
            int idx = tid + j * GT;
            int r = idx >> 3;
            int col = (idx & 7) * 4;
            int offA = r * ROWB_A + col * 2;
            float4 v = aR[j];
            float hx = __bfloat162float(__float2bfloat16(v.x));
            float hy = __bfloat162float(__float2bfloat16(v.y));
            float hz = __bfloat162float(__float2bfloat16(v.z));
            float hw = __bfloat162float(__float2bfloat16(v.w));
            *reinterpret_cast<uint2*>(st + offA) =
                make_uint2(pack2(hx, hy), pack2(hz, hw));
            *reinterpret_cast<uint2*>(st + A_TILE + offA) =
                make_uint2(pack2(v.x - hx, v.y - hy), pack2(v.z - hz, v.w - hw));
        }
#pragma unroll
        for (int j = 0; j < 4; j++) {
            int idx = tid + j * GT;
            int br = idx >> 5;
            int bcol = (idx & 31) * 4;
            int offB = B_OFF + br * ROWB_B + bcol * 2;
            float4 w = bR[j];
            float gx = __bfloat162float(__float2bfloat16(w.x));
            float gy = __bfloat162float(__float2bfloat16(w.y));
            float gz = __bfloat162float(__float2bfloat16(w.z));
            float gw = __bfloat162float(__float2bfloat16(w.w));
            *reinterpret_cast<uint2*>(st + offB) =
                make_uint2(pack2(gx, gy), pack2(gz, gw));
            *reinterpret_cast<uint2*>(st + B_TILE + offB) =
                make_uint2(pack2(w.x - gx, w.y - gy), pack2(w.z - gz, w.w - gw));
        }
    };

    gload(0);
    sstore(0);
    __syncthreads();

    for (int c = 0; c < nch; c++) {
        const int s = c & 1;
        const uint32_t stoff = (uint32_t)s * STAGE_B;
        if (c + 1 < nch) gload(c + 1);

#pragma unroll
        for (int ks = 0; ks < 2; ks++) {
            uint32_t ah[2][4], al[2][4];
#pragma unroll
            for (int mt = 0; mt < 2; mt++) {
                ldsm_x4(ah[mt], aBase + stoff + mt * 16 * ROWB_A + ks * 32);
                ldsm_x4(al[mt], aBase + stoff + A_TILE + mt * 16 * ROWB_A + ks * 32);
            }
#pragma unroll
            for (int nq = 0; nq < 2; nq++) {
                uint32_t bh[4], bl[4];
                uint32_t ad = bBase + stoff + ks * 16 * ROWB_B
                            + (uint32_t)((warp_n * 32 + nq * 16) * 2);
                ldsm_x4_t(bh, ad);
                ldsm_x4_t(bl, ad + B_TILE);
#pragma unroll
                for (int mt = 0; mt < 2; mt++) {
#pragma unroll
                    for (int half = 0; half < 2; half++) {
                        int nt = nq * 2 + half;
                        mma_bf16(acc[mt][nt], ah[mt], &bh[half * 2]);
                        mma_bf16(acc[mt][nt], ah[mt], &bl[half * 2]);
                        mma_bf16(acc[mt][nt], al[mt], &bh[half * 2]);
                    }
                }
            }
        }
        if (c + 1 < nch) sstore((c + 1) & 1);
        __syncthreads();
    }

    const int g = lane >> 2;
    const int tc2 = (lane & 3) * 2;

    if (REDUCE) {
        float* sred = reinterpret_cast<float*>(smem);
        float part[2][2] = {{0.f, 0.f}, {0.f, 0.f}};
#pragma unroll
        for (int mt = 0; mt < 2; mt++) {
#pragma unroll
            for (int nt = 0; nt < 4; nt++) {
                int col = warp_n * 32 + nt * 8 + tc2;
                float w0 = __ldg(rb2 + col), w1 = __ldg(rb2 + col + 1);
                float b0 = __ldg(rb1 + col), b1 = __ldg(rb1 + col + 1);
                float wl0 = 0.f, wl1 = 0.f;
                if (GHLD) { wl0 = __ldg(wld + col); wl1 = __ldg(wld + col + 1); }
#pragma unroll
                for (int h = 0; h < 2; h++) {
                    int row = rowBase + warp_m * 32 + mt * 16 + h * 8 + g;
                    float v0 = acc[mt][nt][h * 2 + 0] + b0;
                    float v1 = acc[mt][nt][h * 2 + 1] + b1;
                    if (GHLD) {
                        int n = row >> 2;
                        float ldv = __ldg(ldg_ + row);
                        v0 += gh[(size_t)n * GATEH + col]     + ldv * wl0;
                        v1 += gh[(size_t)n * GATEH + col + 1] + ldv * wl1;
                    }
                    v0 = fmaxf(v0, 0.f); v1 = fmaxf(v1, 0.f);
                    part[mt][h] += v0 * w0 + v1 * w1;
                }
            }
        }
#pragma unroll
        for (int mt = 0; mt < 2; mt++)
#pragma unroll
            for (int h = 0; h < 2; h++) {
                float p = part[mt][h];
                p += __shfl_xor_sync(0xFFFFFFFFu, p, 1);
                p += __shfl_xor_sync(0xFFFFFFFFu, p, 2);
                if ((lane & 3) == 0)
                    sred[(warp_m * 32 + mt * 16 + h * 8 + g) * 4 + warp_n] = p;
            }
        __syncthreads();
        if (tid < 64) {
            int row = rowBase + tid;
            if (row < M) {
                float sv = sred[tid * 4] + sred[tid * 4 + 1]
                         + sred[tid * 4 + 2] + sred[tid * 4 + 3] + __ldg(rb3);
                C1[row] = sv;
            }
        }
        return;
    }

#pragma unroll
    for (int mt = 0; mt < 2; mt++) {
#pragma unroll
        for (int nt = 0; nt < 4; nt++) {
            int row0 = rowBase + warp_m * 32 + mt * 16 + g;
            int col = cb + warp_n * 32 + nt * 8 + tc2;
            float c0 = acc[mt][nt][0], c1 = acc[mt][nt][1];
            float c2 = acc[mt][nt][2], c3 = acc[mt][nt][3];
            if (BIAS) {
                float2 bb = *reinterpret_cast<const float2*>(bias + col);
                c0 += bb.x; c1 += bb.y; c2 += bb.x; c3 += bb.y;
            }
            if (RELU) {
                c0 = fmaxf(c0, 0.f); c1 = fmaxf(c1, 0.f);
                c2 = fmaxf(c2, 0.f); c3 = fmaxf(c3, 0.f);
            }
            if (row0 < M)
                *reinterpret_cast<float2*>(Cp + (size_t)row0 * N + col) = make_float2(c0, c1);
            if (row0 + 8 < M)
                *reinterpret_cast<float2*>(Cp + (size_t)(row0 + 8) * N + col) = make_float2(c2, c3);
        }
    }
}

// ============ fused gather + G-GEMM + gate-score epilogue ============
// grid (1250), 256 thr. Each CTA: 64 (n,k)-rows. Gathers A rows from CSR into
// persistent full-K smem tile (hi/lo), writes clipped fp32 rows to Mb,
// then 4-chunk mainloop with B double-buffer, gate-score REDUCE epilogue.
#define GG_ROWB 272
#define GG_A_TILE (64 * GG_ROWB)            // 17408 per plane
#define GG_B_TILE (32 * GG_ROWB)            // 8704 per plane
#define GG_B_OFF  (2 * GG_A_TILE)           // 34816
#define GG_BSTAGE (2 * GG_B_TILE)           // 17408
#define GG_SMEM   (GG_B_OFF + 2 * GG_BSTAGE) // 69632

__global__ __launch_bounds__(GT, 2) void gather_gemm(
    const int* __restrict__ off, const int* __restrict__ ecol,
    const float* __restrict__ Z, float* __restrict__ Mb,
    const float* __restrict__ B1,
    const float* __restrict__ gh, const float* __restrict__ ldg_,
    const float* __restrict__ wld, const float* __restrict__ rb1,
    const float* __restrict__ rb2, const float* __restrict__ rb3,
    float* __restrict__ scores)
{
    extern __shared__ __align__(128) char smem[];
    const int tid = threadIdx.x;
    const int lane = tid & 31;
    const int wid = tid >> 5;
    const int warp_m = wid & 1;
    const int warp_n = wid >> 1;
    const int rowBase = blockIdx.x * 64;
    const uint32_t sb = smem_u32(smem);

    // ---- prologue: gather 8 rows per warp into A tile + Mb
#pragma unroll
    for (int r = 0; r < 8; r++) {
        int rl = wid * 8 + r;
        int row = rowBase + rl;
        int n = row >> 2, k = row & 3;
        int w = k * N_NODES + n;
        int s = off[w], t = off[w + 1];
        float4 a0 = make_float4(0.f, 0.f, 0.f, 0.f);
        float4 a1 = make_float4(0.f, 0.f, 0.f, 0.f);
        int e = s;
        for (; e + 2 <= t; e += 2) {
            int c0 = ecol[e], c1 = ecol[e + 1];
            float4 v0 = reinterpret_cast<const float4*>(Z + (size_t)c0 * DDIM)[lane];
            float4 v1 = reinterpret_cast<const float4*>(Z + (size_t)c1 * DDIM)[lane];
            a0.x += v0.x; a0.y += v0.y; a0.z += v0.z; a0.w += v0.w;
            a1.x += v1.x; a1.y += v1.y; a1.z += v1.z; a1.w += v1.w;
        }
        if (e < t) {
            int c0 = ecol[e];
            float4 v0 = reinterpret_cast<const float4*>(Z + (size_t)c0 * DDIM)[lane];
            a0.x += v0.x; a0.y += v0.y; a0.z += v0.z; a0.w += v0.w;
        }
        float4 rv;
        rv.x = fminf(fmaxf(a0.x + a1.x, -MCLAMP), MCLAMP);
        rv.y = fminf(fmaxf(a0.y + a1.y, -MCLAMP), MCLAMP);
        rv.z = fminf(fmaxf(a0.z + a1.z, -MCLAMP), MCLAMP);
        rv.w = fminf(fmaxf(a0.w + a1.w, -MCLAMP), MCLAMP);
        reinterpret_cast<float4*>(Mb + (size_t)row * DDIM)[lane] = rv;
        float hx = __bfloat162float(__float2bfloat16(rv.x));
        float hy = __bfloat162float(__float2bfloat16(rv.y));
        float hz = __bfloat162float(__float2bfloat16(rv.z));
        float hw = __bfloat162float(__float2bfloat16(rv.w));
        int offA = rl * GG_ROWB + lane * 8;
        *reinterpret_cast<uint2*>(smem + offA) =
            make_uint2(pack2(hx, hy), pack2(hz, hw));
        *reinterpret_cast<uint2*>(smem + GG_A_TILE + offA) =
            make_uint2(pack2(rv.x - hx, rv.y - hy), pack2(rv.z - hz, rv.w - hw));
    }

    float acc[2][4][4];
#pragma unroll
    for (int i = 0; i < 2; i++)
#pragma unroll
        for (int j = 0; j < 4; j++)
#pragma unroll
            for (int q = 0; q < 4; q++) acc[i][j][q] = 0.f;

    const int aRow = warp_m * 32 + (lane & 7) + ((lane >> 3) & 1) * 8;
    const int aK   = ((lane >> 4) & 1) * 8;
    const uint32_t aBase = sb + (uint32_t)(aRow * GG_ROWB + aK * 2);
    const uint32_t bLane = (uint32_t)((lane & 15) * GG_ROWB + (lane >> 4) * 16);

    float4 bR[4];
    auto bload = [&](int c) {
#pragma unroll
        for (int j = 0; j < 4; j++) {
            int idx = tid + j * GT;
            int br = idx >> 5;
            int bcol = (idx & 31) * 4;
            bR[j] = *reinterpret_cast<const float4*>(B1 + (size_t)(c * 32 + br) * GATEH + bcol);
        }
    };
    auto bstore = [&](int s) {
        char* st = smem + GG_B_OFF + s * GG_BSTAGE;
#pragma unroll
        for (int j = 0; j < 4; j++) {
            int idx = tid + j * GT;
            int br = idx >> 5;
            int bcol = (idx & 31) * 4;
            int offB = br * GG_ROWB + bcol * 2;
            float4 w = bR[j];
            float gx = __bfloat162float(__float2bfloat16(w.x));
            float gy = __bfloat162float(__float2bfloat16(w.y));
            float gz = __bfloat162float(__float2bfloat16(w.z));
            float gw = __bfloat162float(__float2bfloat16(w.w));
            *reinterpret_cast<uint2*>(st + offB) =
                make_uint2(pack2(gx, gy), pack2(gz, gw));
            *reinterpret_cast<uint2*>(st + GG_B_TILE + offB) =
                make_uint2(pack2(w.x - gx, w.y - gy), pack2(w.z - gz, w.w - gw));
        }
    };

    bload(0);
    bstore(0);
    __syncthreads();

#pragma unroll
    for (int c = 0; c < 4; c++) {
        const uint32_t stB = sb + (uint32_t)(GG_B_OFF + (c & 1) * GG_BSTAGE);
        if (c + 1 < 4) bload(c + 1);

#pragma unroll
        for (int ks = 0; ks < 2; ks++) {
            uint32_t ah[2][4], al[2][4];
#pragma unroll
            for (int mt = 0; mt < 2; mt++) {
                uint32_t ad = aBase + (uint32_t)(mt * 16 * GG_ROWB + c * 64 + ks * 32);
                ldsm_x4(ah[mt], ad);
                ldsm_x4(al[mt], ad + GG_A_TILE);
            }
#pragma unroll
            for (int nq = 0; nq < 2; nq++) {
                uint32_t bh[4], bl[4];
                uint32_t ad = stB + bLane + (uint32_t)(ks * 16 * GG_ROWB + (warp_n * 32 + nq * 16) * 2);
                ldsm_x4_t(bh, ad);
                ldsm_x4_t(bl, ad + GG_B_TILE);
#pragma unroll
                for (int mt = 0; mt < 2; mt++) {
#pragma unroll
                    for (int half = 0; half < 2; half++) {
                        int nt = nq * 2 + half;
                        mma_bf16(acc[mt][nt], ah[mt], &bh[half * 2]);
                        mma_bf16(acc[mt][nt], ah[mt], &bl[half * 2]);
                        mma_bf16(acc[mt][nt], al[mt], &bh[half * 2]);
                    }
                }
            }
        }
        if (c + 1 < 4) bstore((c + 1) & 1);
        __syncthreads();
    }

    // ---- gate-score epilogue (GHLD)
    const int g = lane >> 2;
    const int tc2 = (lane & 3) * 2;
    float* sred = reinterpret_cast<float*>(smem);
    float part[2][2] = {{0.f, 0.f}, {0.f, 0.f}};
#pragma unroll
    for (int mt = 0; mt < 2; mt++) {
#pragma unroll
        for (int nt = 0; nt < 4; nt++) {
            int col = warp_n * 32 + nt * 8 + tc2;
            float w0 = __ldg(rb2 + col), w1 = __ldg(rb2 + col + 1);
            float b0 = __ldg(rb1 + col), b1 = __ldg(rb1 + col + 1);
            float wl0 = __ldg(wld + col), wl1 = __ldg(wld + col + 1);
#pragma unroll
            for (int h = 0; h < 2; h++) {
                int row = rowBase + warp_m * 32 + mt * 16 + h * 8 + g;
                int n = row >> 2;
                float ldv = __ldg(ldg_ + row);
                float v0 = acc[mt][nt][h * 2 + 0] + b0 + gh[(size_t)n * GATEH + col]     + ldv * wl0;
                float v1 = acc[mt][nt][h * 2 + 1] + b1 + gh[(size_t)n * GATEH + col + 1] + ldv * wl1;
                v0 = fmaxf(v0, 0.f); v1 = fmaxf(v1, 0.f);
                part[mt][h] += v0 * w0 + v1 * w1;
            }
        }
    }
#pragma unroll
    for (int mt = 0; mt < 2; mt++)
#pragma unroll
        for (int h = 0; h < 2; h++) {
            float p = part[mt][h];
            p += __shfl_xor_sync(0xFFFFFFFFu, p, 1);
            p += __shfl_xor_sync(0xFFFFFFFFu, p, 2);
            if ((lane & 3) == 0)
                sred[(warp_m * 32 + mt * 16 + h * 8 + g) * 4 + warp_n] = p;
        }
    __syncthreads();
    if (tid < 64) {
        int row = rowBase + tid;
        float sv = sred[tid * 4] + sred[tid * 4 + 1]
                 + sred[tid * 4 + 2] + sred[tid * 4 + 3] + __ldg(rb3);
        scores[row] = sv;
    }
}

// ================= CSR build =================
#define SCB 160
#define SCT 256
#define SPT 2

__global__ void zero_int_kernel(int* p, int n, int* q, int m, int* dn) {
    int i = blockIdx.x * blockDim.x + threadIdx.x;
    if (i < n) p[i] = 0;
    if (i < m) q[i] = 0;
    if (i < 2) dn[i] = 0;
}
__global__ void hist_kernel(const int* __restrict__ rows, int* __restrict__ cnt) {
    int i = blockIdx.x * blockDim.x + threadIdx.x;
    if (i >= K_REL * E_EDGES) return;
    int k = i / E_EDGES;
    atomicAdd(&cnt[k * N_NODES + rows[i]], 1);
}
__global__ __launch_bounds__(SCT) void scan_part(const int* __restrict__ cnt, int* __restrict__ bsum)
{
    __shared__ int ss[SCT];
    int b = blockIdx.x, t = threadIdx.x;
    int base = b * SCT * SPT + t * SPT;
    int local = 0;
#pragma unroll
    for (int i = 0; i < SPT; i++) {
        int idx = base + i;
        if (idx < NBUCKET) local += cnt[idx];
    }
    ss[t] = local; __syncthreads();
    for (int d = SCT >> 1; d > 0; d >>= 1) {
        if (t < d) ss[t] += ss[t + d];
        __syncthreads();
    }
    if (t == 0) bsum[b] = ss[0];
}
__global__ __launch_bounds__(SCT) void scan_top(const int* __restrict__ bsum,
                                                int* __restrict__ btop, int* __restrict__ off)
{
    __shared__ int ss[SCT];
    int t = threadIdx.x;
    int v = (t < SCB) ? bsum[t] : 0;
    ss[t] = v; __syncthreads();
    for (int d = 1; d < SCT; d <<= 1) {
        int u = (t >= d) ? ss[t - d] : 0;
        __syncthreads();
        ss[t] += u;
        __syncthreads();
    }
    if (t < SCB) btop[t] = ss[t] - v;
    if (t == SCB - 1) off[NBUCKET] = ss[t];
}
__global__ __launch_bounds__(SCT) void scan_write(const int* __restrict__ cnt,
                                                  const int* __restrict__ btop,
                                                  int* __restrict__ off, int* __restrict__ cur)
{
    __shared__ int ss[SCT];
    int b = blockIdx.x, t = threadIdx.x;
    int base = b * SCT * SPT + t * SPT;
    int c[SPT];
    int local = 0;
#pragma unroll
    for (int i = 0; i < SPT; i++) {
        int idx = base + i;
        c[i] = (idx < NBUCKET) ? cnt[idx] : 0;
        local += c[i];
    }
    ss[t] = local; __syncthreads();
    for (int d = 1; d < SCT; d <<= 1) {
        int u = (t >= d) ? ss[t - d] : 0;
        __syncthreads();
        ss[t] += u;
        __syncthreads();
    }
    int run = btop[b] + ss[t] - local;
#pragma unroll
    for (int i = 0; i < SPT; i++) {
        int idx = base + i;
        if (idx < NBUCKET) { off[idx] = run; cur[idx] = run; run += c[i]; }
    }
}
__global__ void fill_kernel(const int* __restrict__ rows, const int* __restrict__ cols,
                            int* __restrict__ cur, int* __restrict__ ecol)
{
    int i = blockIdx.x * blockDim.x + threadIdx.x;
    if (i >= K_REL * E_EDGES) return;
    int k = i / E_EDGES;
    int p = atomicAdd(&cur[k * N_NODES + rows[i]], 1);
    ecol[p] = cols[i];
}

// ===== fused: softmax + weighted sum + residual (+pairnorm of H input) + stats tail =====
#define FUSE_NPB 16
template <bool HNORM>
__global__ __launch_bounds__(DDIM) void fused_kernel(
    const float* __restrict__ Mb, const float* __restrict__ scores,
    const float* __restrict__ mask,
    const float* __restrict__ Hsrc, const float* __restrict__ hstats,
    float* __restrict__ Xres,
    float* __restrict__ colsum, float* __restrict__ alpha_out,
    int* __restrict__ done, float* __restrict__ stats_out)
{
    int d = threadIdx.x;
    int n0 = blockIdx.x * FUSE_NPB;
    __shared__ float a[FUSE_NPB][K_REL];
    __shared__ float wsum[4];
    __shared__ int slast;
    float hmu = 0.f, hinv = 0.f;
    if (HNORM) { hmu = hstats[d]; hinv = hstats[DDIM]; }
    if (d < FUSE_NPB) {
        int n = n0 + d;
        float s[K_REL], aa[K_REL];
        float m = -1e30f;
#pragma unroll
        for (int k = 0; k < K_REL; k++) { s[k] = scores[n * K_REL + k] * TEMP_INV; m = fmaxf(m, s[k]); }
        float sum = 0.f;
#pragma unroll
        for (int k = 0; k < K_REL; k++) { aa[k] = __expf(s[k] - m); sum += aa[k]; }
        float inv = 1.f / sum;
        float sum2 = 0.f;
#pragma unroll
        for (int k = 0; k < K_REL; k++) { aa[k] = aa[k] * inv * mask[n * K_REL + k]; sum2 += aa[k]; }
        float inv2 = 1.f / fmaxf(sum2, 1e-12f);
        float sum3 = 0.f;
#pragma unroll
        for (int k = 0; k < K_REL; k++) { aa[k] = fmaxf(aa[k] * inv2, 1e-8f); sum3 += aa[k]; }
        float inv3 = 1.f / fmaxf(sum3, 1e-12f);
#pragma unroll
        for (int k = 0; k < K_REL; k++) { aa[k] *= inv3; a[d][k] = aa[k]; }
        *reinterpret_cast<float4*>(alpha_out + (size_t)n * K_REL) =
            make_float4(aa[0], aa[1], aa[2], aa[3]);
    }
    __syncthreads();
    float csum = 0.f, qsum = 0.f;
#pragma unroll
    for (int i = 0; i < FUSE_NPB; i++) {
        int n = n0 + i;
        if (n >= N_NODES) break;
        float f = 0.f;
#pragma unroll
        for (int k = 0; k < K_REL; k++)
            f += a[i][k] * Mb[((size_t)n * K_REL + k) * DDIM + d];
        float h = Hsrc[(size_t)n * DDIM + d];
        if (HNORM) h = fmaxf((h - hmu) * hinv, 0.f);
        float x = f + h;
        Xres[(size_t)n * DDIM + d] = x;
        csum += x;
        qsum += x * x;
    }
    atomicAdd(&colsum[d], csum);
#pragma unroll
    for (int o = 16; o > 0; o >>= 1) qsum += __shfl_xor_sync(0xFFFFFFFFu, qsum, o);
    if ((d & 31) == 0) wsum[d >> 5] = qsum;
    __syncthreads();
    if (d == 0) {
        atomicAdd(&colsum[DDIM], wsum[0] + wsum[1] + wsum[2] + wsum[3]);
        __threadfence();
        slast = (atomicAdd(done, 1) == (int)gridDim.x - 1) ? 1 : 0;
    }
    __syncthreads();
    if (slast) {
        float mu = colsum[d] * (1.0f / N_NODES);
        stats_out[d] = mu;
        float q = mu * mu;
#pragma unroll
        for (int o = 16; o > 0; o >>= 1) q += __shfl_xor_sync(0xFFFFFFFFu, q, o);
        if ((d & 31) == 0) wsum[d >> 5] = q;
        __syncthreads();
        if (d == 0) {
            float summu2 = wsum[0] + wsum[1] + wsum[2] + wsum[3];
            float var = (colsum[DDIM] - (float)N_NODES * summu2) * (1.0f / N_NODES);
            var = fmaxf(var, 0.f);
            stats_out[DDIM] = 1.0f / (sqrtf(var) + 1e-6f);
        }
    }
}

// ================= host =================
extern "C" void kernel_launch(void* const* d_in, const int* in_sizes, int n_in,
                              void* d_out, int out_size)
{
    const float* X      = (const float*)d_in[0];
    const int*   rows   = (const int*)d_in[1];
    const int*   cols   = (const int*)d_in[2];
    const float* mask   = (const float*)d_in[3];
    const float* logdeg = (const float*)d_in[4];
    const float* W_in0  = (const float*)d_in[5];
    const float* b_in0  = (const float*)d_in[6];
    const float* W_in1  = (const float*)d_in[7];
    const float* b_in1  = (const float*)d_in[8];
    const float* W_in2  = (const float*)d_in[9];
    const float* b_in2  = (const float*)d_in[10];
    const float* Wmsg[2]  = {(const float*)d_in[11], (const float*)d_in[16]};
    const float* Wg1[2]   = {(const float*)d_in[12], (const float*)d_in[17]};
    const float* bg1[2]   = {(const float*)d_in[13], (const float*)d_in[18]};
    const float* Wg2[2]   = {(const float*)d_in[14], (const float*)d_in[19]};
    const float* bg2[2]   = {(const float*)d_in[15], (const float*)d_in[20]};
    const float* Wh1    = (const float*)d_in[21];
    const float* bh1    = (const float*)d_in[22];
    const float* Wh2    = (const float*)d_in[23];
    const float* bh2    = (const float*)d_in[24];
    float* out = (float*)d_out;

    float *buf0, *buf1, *H, *Z, *Mb, *gateH, *scores, *Xres, *colsum, *stats;
    int *cnt, *off, *cur, *ecol, *bsum, *btop, *done;
    cudaGetSymbolAddress((void**)&buf0,  g_buf0);
    cudaGetSymbolAddress((void**)&buf1,  g_buf1);
    cudaGetSymbolAddress((void**)&H,     g_H);
    cudaGetSymbolAddress((void**)&Z,     g_Z);
    cudaGetSymbolAddress((void**)&Mb,    g_M);
    cudaGetSymbolAddress((void**)&gateH, g_gateH);
    cudaGetSymbolAddress((void**)&scores,g_scores);
    cudaGetSymbolAddress((void**)&Xres,  g_Xres);
    cudaGetSymbolAddress((void**)&colsum,g_colsum);
    cudaGetSymbolAddress((void**)&stats, g_stats);
    cudaGetSymbolAddress((void**)&done,  g_done);
    cudaGetSymbolAddress((void**)&cnt,   g_cnt);
    cudaGetSymbolAddress((void**)&off,   g_off);
    cudaGetSymbolAddress((void**)&cur,   g_cur);
    cudaGetSymbolAddress((void**)&ecol,  g_ecol);
    cudaGetSymbolAddress((void**)&bsum,  g_bsum);
    cudaGetSymbolAddress((void**)&btop,  g_btop);

    cudaFuncSetAttribute(mma_gemm<true,true,false,false,false,false>,  cudaFuncAttributeMaxDynamicSharedMemorySize, GEMM_SMEM);
    cudaFuncSetAttribute(mma_gemm<false,false,true,false,false,false>, cudaFuncAttributeMaxDynamicSharedMemorySize, GEMM_SMEM);
    cudaFuncSetAttribute(mma_gemm<false,false,true,false,false,true>,  cudaFuncAttributeMaxDynamicSharedMemorySize, GEMM_SMEM);
    cudaFuncSetAttribute(mma_gemm<false,false,false,true,false,true>,  cudaFuncAttributeMaxDynamicSharedMemorySize, GEMM_SMEM);
    cudaFuncSetAttribute(gather_gemm, cudaFuncAttributeMaxDynamicSharedMemorySize, GG_SMEM);

    const int MT = (N_NODES + 63) / 64;           // 313
    const int GGB = (N_NODES * K_REL) / 64;       // 1250
    const int FUSEB = (N_NODES + FUSE_NPB - 1) / FUSE_NPB;

    // 0-2: CSR front half (+ colsum/done zeroing)
    zero_int_kernel<<<(NBUCKET + 255) / 256, 256>>>(cnt, NBUCKET, (int*)colsum, 2 * SSTRIDE, done);
    hist_kernel<<<(K_REL * E_EDGES + 255) / 256, 256>>>(rows, cnt);
    scan_part<<<SCB, SCT>>>(cnt, bsum);

    // 3 (profiled): encoder GEMM 1
    mma_gemm<true,true,false,false,false,false><<<dim3(2, MT), GT, GEMM_SMEM>>>(
        X, W_in0, b_in0, buf0, N_NODES, INDIM, HINDIM, nullptr, nullptr,
        nullptr, nullptr, nullptr, nullptr, nullptr, nullptr, nullptr);

    // 4-6: CSR back half
    scan_top<<<1, SCT>>>(bsum, btop, off);
    scan_write<<<SCB, SCT>>>(cnt, btop, off, cur);
    fill_kernel<<<(K_REL * E_EDGES + 255) / 256, 256>>>(rows, cols, cur, ecol);

    // 7-8: encoder GEMMs 2-3
    mma_gemm<true,true,false,false,false,false><<<dim3(2, MT), GT, GEMM_SMEM>>>(
        buf0, W_in1, b_in1, buf1, N_NODES, HINDIM, HINDIM, nullptr, nullptr,
        nullptr, nullptr, nullptr, nullptr, nullptr, nullptr, nullptr);
    mma_gemm<true,true,false,false,false,false><<<dim3(1, MT), GT, GEMM_SMEM>>>(
        buf1, W_in2, b_in2, H, N_NODES, HINDIM, DDIM, nullptr, nullptr,
        nullptr, nullptr, nullptr, nullptr, nullptr, nullptr, nullptr);

    // ---- block 0 ----
    mma_gemm<false,false,true,false,false,false><<<dim3(2, MT), GT, GEMM_SMEM>>>(
        H, Wmsg[0], nullptr, Z, N_NODES, DDIM, DDIM, Wg1[0], gateH,
        nullptr, nullptr, nullptr, nullptr, nullptr, nullptr, nullptr);
    gather_gemm<<<GGB, GT, GG_SMEM>>>(
        off, ecol, Z, Mb, Wg1[0] + DDIM * GATEH,
        gateH, logdeg, Wg1[0] + 2 * DDIM * GATEH, bg1[0], Wg2[0], bg2[0], scores);
    fused_kernel<false><<<FUSEB, DDIM>>>(
        Mb, scores, mask, H, nullptr, Xres, colsum,
        out + N_NODES, done, stats);

    // ---- block 1 (pairnorm folded into consumers) ----
    mma_gemm<false,false,true,false,false,true><<<dim3(2, MT), GT, GEMM_SMEM>>>(
        Xres, Wmsg[1], nullptr, Z, N_NODES, DDIM, DDIM, Wg1[1], gateH,
        nullptr, nullptr, nullptr, nullptr, nullptr, nullptr, stats);
    gather_gemm<<<GGB, GT, GG_SMEM>>>(
        off, ecol, Z, Mb, Wg1[1] + DDIM * GATEH,
        gateH, logdeg, Wg1[1] + 2 * DDIM * GATEH, bg1[1], Wg2[1], bg2[1], scores);
    fused_kernel<true><<<FUSEB, DDIM>>>(
        Mb, scores, mask, Xres, stats, Xres, colsum + SSTRIDE,
        out + N_NODES + (size_t)N_NODES * K_REL, done + 1, stats + SSTRIDE);

    // ---- head ----
    mma_gemm<false,false,false,true,false,true><<<dim3(1, MT), GT, GEMM_SMEM>>>(
        Xres, Wh1, nullptr, out, N_NODES, DDIM, DDIM, nullptr, nullptr,
        nullptr, nullptr, nullptr, bh1, Wh2, bh2, stats + SSTRIDE);
}

// round 16
// speedup vs baseline: 1.0406x; 1.0406x over previous
#include <cuda_runtime.h>
#include <cuda_bf16.h>
#include <math.h>
#include <cstdint>

#define N_NODES 20000
#define K_REL   4
#define E_EDGES 320000
#define INDIM   1024
#define HINDIM  256
#define DDIM    128
#define GATEH   128
#define TEMP_INV (1.0f/0.6f)
#define MCLAMP  20.0f
#define NBUCKET (K_REL * N_NODES)
#define SSTRIDE 132

// ---------------- scratch ----------------
__device__ float g_buf0[N_NODES * HINDIM];
__device__ float g_buf1[N_NODES * HINDIM];
__device__ float g_H[N_NODES * DDIM];
__device__ float g_Z[N_NODES * DDIM];
__device__ float g_M[N_NODES * K_REL * DDIM];
__device__ float g_gateH[N_NODES * GATEH];
__device__ float g_scores[N_NODES * K_REL];
__device__ float g_Xres[N_NODES * DDIM];
__device__ __align__(16) float g_colsum[2 * SSTRIDE];
__device__ __align__(16) float g_stats[2 * SSTRIDE];
__device__ int   g_done[2];
// CSR
__device__ int g_cnt[NBUCKET];
__device__ int g_off[NBUCKET + 1];
__device__ int g_cur[NBUCKET];
__device__ int g_ecol[K_REL * E_EDGES];
__device__ int g_bsum[256];
__device__ int g_btop[256];

// ================= helpers =================
__device__ __forceinline__ uint32_t smem_u32(const void* p) {
    uint32_t a;
    asm("{ .reg .u64 t; cvta.to.shared.u64 t, %1; cvt.u32.u64 %0, t; }" : "=r"(a) : "l"(p));
    return a;
}
__device__ __forceinline__ void ldsm_x4(uint32_t* r, uint32_t addr) {
    asm volatile("ldmatrix.sync.aligned.m8n8.x4.shared.b16 {%0,%1,%2,%3}, [%4];"
        : "=r"(r[0]), "=r"(r[1]), "=r"(r[2]), "=r"(r[3]) : "r"(addr));
}
__device__ __forceinline__ void ldsm_x4_t(uint32_t* r, uint32_t addr) {
    asm volatile("ldmatrix.sync.aligned.m8n8.x4.trans.shared.b16 {%0,%1,%2,%3}, [%4];"
        : "=r"(r[0]), "=r"(r[1]), "=r"(r[2]), "=r"(r[3]) : "r"(addr));
}
__device__ __forceinline__ void mma_bf16(float* c, const uint32_t* a, const uint32_t* b) {
    asm volatile("mma.sync.aligned.m16n8k16.row.col.f32.bf16.bf16.f32 "
        "{%0,%1,%2,%3}, {%4,%5,%6,%7}, {%8,%9}, {%0,%1,%2,%3};"
        : "+f"(c[0]), "+f"(c[1]), "+f"(c[2]), "+f"(c[3])
        : "r"(a[0]), "r"(a[1]), "r"(a[2]), "r"(a[3]), "r"(b[0]), "r"(b[1]));
}
__device__ __forceinline__ uint32_t pack2(float a, float b) {
    __nv_bfloat162 h = __floats2bfloat162_rn(a, b);
    return *reinterpret_cast<uint32_t*>(&h);
}

// ================= bf16 3-split GEMM: BM=64, BN=128, 256 threads =================
#define GT 256
#define ROWB_A 80
#define ROWB_B 272
#define A_TILE (64 * ROWB_A)
#define B_TILE (32 * ROWB_B)
#define STAGE_B (2 * A_TILE + 2 * B_TILE)   // 27648
#define GEMM_SMEM (2 * STAGE_B)             // 55296
#define B_OFF (2 * A_TILE)

template <bool RELU, bool BIAS, bool DUAL, bool REDUCE, bool GHLD, bool ANORM>
__global__ __launch_bounds__(GT, 2) void mma_gemm(
    const float* __restrict__ A, const float* __restrict__ B1,
    const float* __restrict__ bias, float* __restrict__ C1,
    int M, int K, int N,
    const float* __restrict__ B2, float* __restrict__ C2,
    const float* __restrict__ gh, const float* __restrict__ ldg_,
    const float* __restrict__ wld, const float* __restrict__ rb1,
    const float* __restrict__ rb2, const float* __restrict__ rb3,
    const float* __restrict__ anorm_stats)
{
    extern __shared__ __align__(128) char smem[];
    const int tid = threadIdx.x;
    const int lane = tid & 31;
    const int wid = tid >> 5;
    const int warp_m = wid & 1;
    const int warp_n = wid >> 1;
    const int rowBase = blockIdx.y * 64;
    const int nch = K >> 5;

    const float* Bp = B1;
    float* Cp = C1;
    int cb = blockIdx.x * 128;
    if (DUAL) {
        if (blockIdx.x == 1) { Bp = B2; Cp = C2; }
        cb = 0;
    }

    float anorm_inv = 0.f;
    if (ANORM) anorm_inv = __ldg(anorm_stats + DDIM);

    float acc[2][4][4];
#pragma unroll
    for (int i = 0; i < 2; i++)
#pragma unroll
        for (int j = 0; j < 4; j++)
#pragma unroll
            for (int q = 0; q < 4; q++) acc[i][j][q] = 0.f;

    const uint32_t sb = smem_u32(smem);
    const int aRow = warp_m * 32 + (lane & 7) + ((lane >> 3) & 1) * 8;
    const int aK   = ((lane >> 4) & 1) * 8;
    const uint32_t aBase = sb + (uint32_t)(aRow * ROWB_A + aK * 2);
    const uint32_t bBase = sb + (uint32_t)B_OFF
                         + (uint32_t)((lane & 15) * ROWB_B + (lane >> 4) * 16);

    float4 aR[2], bR[4];

    auto gload = [&](int c) {
        const int k0 = c << 5;
#pragma unroll
        for (int j = 0; j < 2; j++) {
            int idx = tid + j * GT;
            int r = idx >> 3;
            int col = (idx & 7) * 4;
            int gr = rowBase + r;
            float4 v = make_float4(0.f, 0.f, 0.f, 0.f);
            if (gr < M) {
                v = *reinterpret_cast<const float4*>(A + (size_t)gr * K + k0 + col);
                if (ANORM) {
                    float4 mu = *reinterpret_cast<const float4*>(anorm_stats + k0 + col);
                    v.x = fmaxf((v.x - mu.x) * anorm_inv, 0.f);
                    v.y = fmaxf((v.y - mu.y) * anorm_inv, 0.f);
                    v.z = fmaxf((v.z - mu.z) * anorm_inv, 0.f);
                    v.w = fmaxf((v.w - mu.w) * anorm_inv, 0.f);
                }
            }
            aR[j] = v;
        }
#pragma unroll
        for (int j = 0; j < 4; j++) {
            int idx = tid + j * GT;
            int br = idx >> 5;
            int bcol = (idx & 31) * 4;
            bR[j] = *reinterpret_cast<const float4*>(Bp + (size_t)(k0 + br) * N + cb + bcol);
        }
    };
    auto sstore = [&](int s) {
        char* st = smem + s * STAGE_B;
#pragma unroll
        for (int j = 0; j < 2; j++) {
            int idx = tid + j * GT;
            int r = idx >> 3;
            int col = (idx & 7) * 4;
            int offA = r * ROWB_A + col * 2;
            float4 v = aR[j];
            float hx = __bfloat162float(__float2bfloat16(v.x));
            float hy = __bfloat162float(__float2bfloat16(v.y));
            float hz = __bfloat162float(__float2bfloat16(v.z));
            float hw = __bfloat162float(__float2bfloat16(v.w));
            *reinterpret_cast<uint2*>(st + offA) =
                make_uint2(pack2(hx, hy), pack2(hz, hw));
            *reinterpret_cast<uint2*>(st + A_TILE + offA) =
                make_uint2(pack2(v.x - hx, v.y - hy), pack2(v.z - hz, v.w - hw));
        }
#pragma unroll
        for (int j = 0; j < 4; j++) {
            int idx = tid + j * GT;
            int br = idx >> 5;
            int bcol = (idx & 31) * 4;
            int offB = B_OFF + br * ROWB_B + bcol * 2;
            float4 w = bR[j];
            float gx = __bfloat162float(__float2bfloat16(w.x));
            float gy = __bfloat162float(__float2bfloat16(w.y));
            float gz = __bfloat162float(__float2bfloat16(w.z));
            float gw = __bfloat162float(__float2bfloat16(w.w));
            *reinterpret_cast<uint2*>(st + offB) =
                make_uint2(pack2(gx, gy), pack2(gz, gw));
            *reinterpret_cast<uint2*>(st + B_TILE + offB) =
                make_uint2(pack2(w.x - gx, w.y - gy), pack2(w.z - gz, w.w - gw));
        }
    };

    gload(0);
    sstore(0);
    __syncthreads();

    for (int c = 0; c < nch; c++) {
        const int s = c & 1;
        const uint32_t stoff = (uint32_t)s * STAGE_B;
        if (c + 1 < nch) gload(c + 1);

#pragma unroll
        for (int ks = 0; ks < 2; ks++) {
            uint32_t ah[2][4], al[2][4];
#pragma unroll
            for (int mt = 0; mt < 2; mt++) {
                ldsm_x4(ah[mt], aBase + stoff + mt * 16 * ROWB_A + ks * 32);
                ldsm_x4(al[mt], aBase + stoff + A_TILE + mt * 16 * ROWB_A + ks * 32);
            }
#pragma unroll
            for (int nq = 0; nq < 2; nq++) {
                uint32_t bh[4], bl[4];
                uint32_t ad = bBase + stoff + ks * 16 * ROWB_B
                            + (uint32_t)((warp_n * 32 + nq * 16) * 2);
                ldsm_x4_t(bh, ad);
                ldsm_x4_t(bl, ad + B_TILE);
#pragma unroll
                for (int mt = 0; mt < 2; mt++) {
#pragma unroll
                    for (int half = 0; half < 2; half++) {
                        int nt = nq * 2 + half;
                        mma_bf16(acc[mt][nt], ah[mt], &bh[half * 2]);
                        mma_bf16(acc[mt][nt], ah[mt], &bl[half * 2]);
                        mma_bf16(acc[mt][nt], al[mt], &bh[half * 2]);
                    }
                }
            }
        }
        if (c + 1 < nch) sstore((c + 1) & 1);
        __syncthreads();
    }

    const int g = lane >> 2;
    const int tc2 = (lane & 3) * 2;

    if (REDUCE) {
        float* sred = reinterpret_cast<float*>(smem);
        float part[2][2] = {{0.f, 0.f}, {0.f, 0.f}};
#pragma unroll
        for (int mt = 0; mt < 2; mt++) {
#pragma unroll
            for (int nt = 0; nt < 4; nt++) {
                int col = warp_n * 32 + nt * 8 + tc2;
                float w0 = __ldg(rb2 + col), w1 = __ldg(rb2 + col + 1);
                float b0 = __ldg(rb1 + col), b1 = __ldg(rb1 + col + 1);
                float wl0 = 0.f, wl1 = 0.f;
                if (GHLD) { wl0 = __ldg(wld + col); wl1 = __ldg(wld + col + 1); }
#pragma unroll
                for (int h = 0; h < 2; h++) {
                    int row = rowBase + warp_m * 32 + mt * 16 + h * 8 + g;
                    float v0 = acc[mt][nt][h * 2 + 0] + b0;
                    float v1 = acc[mt][nt][h * 2 + 1] + b1;
                    if (GHLD) {
                        int n = row >> 2;
                        float ldv = __ldg(ldg_ + row);
                        v0 += gh[(size_t)n * GATEH + col]     + ldv * wl0;
                        v1 += gh[(size_t)n * GATEH + col + 1] + ldv * wl1;
                    }
                    v0 = fmaxf(v0, 0.f); v1 = fmaxf(v1, 0.f);
                    part[mt][h] += v0 * w0 + v1 * w1;
                }
            }
        }
#pragma unroll
        for (int mt = 0; mt < 2; mt++)
#pragma unroll
            for (int h = 0; h < 2; h++) {
                float p = part[mt][h];
                p += __shfl_xor_sync(0xFFFFFFFFu, p, 1);
                p += __shfl_xor_sync(0xFFFFFFFFu, p, 2);
                if ((lane & 3) == 0)
                    sred[(warp_m * 32 + mt * 16 + h * 8 + g) * 4 + warp_n] = p;
            }
        __syncthreads();
        if (tid < 64) {
            int row = rowBase + tid;
            if (row < M) {
                float sv = sred[tid * 4] + sred[tid * 4 + 1]
                         + sred[tid * 4 + 2] + sred[tid * 4 + 3] + __ldg(rb3);
                C1[row] = sv;
            }
        }
        return;
    }

#pragma unroll
    for (int mt = 0; mt < 2; mt++) {
#pragma unroll
        for (int nt = 0; nt < 4; nt++) {
            int row0 = rowBase + warp_m * 32 + mt * 16 + g;
            int col = cb + warp_n * 32 + nt * 8 + tc2;
            float c0 = acc[mt][nt][0], c1 = acc[mt][nt][1];
            float c2 = acc[mt][nt][2], c3 = acc[mt][nt][3];
            if (BIAS) {
                float2 bb = *reinterpret_cast<const float2*>(bias + col);
                c0 += bb.x; c1 += bb.y; c2 += bb.x; c3 += bb.y;
            }
            if (RELU) {
                c0 = fmaxf(c0, 0.f); c1 = fmaxf(c1, 0.f);
                c2 = fmaxf(c2, 0.f); c3 = fmaxf(c3, 0.f);
            }
            if (row0 < M)
                *reinterpret_cast<float2*>(Cp + (size_t)row0 * N + col) = make_float2(c0, c1);
            if (row0 + 8 < M)
                *reinterpret_cast<float2*>(Cp + (size_t)(row0 + 8) * N + col) = make_float2(c2, c3);
        }
    }
}

// ================= CSR build =================
#define SCB 160
#define SCT 256
#define SPT 2

__global__ void zero_int_kernel(int* p, int n, int* q, int m, int* dn) {
    int i = blockIdx.x * blockDim.x + threadIdx.x;
    if (i < n) p[i] = 0;
    if (i < m) q[i] = 0;
    if (i < 2) dn[i] = 0;
}
__global__ void hist_kernel(const int* __restrict__ rows, int* __restrict__ cnt) {
    int i = blockIdx.x * blockDim.x + threadIdx.x;
    if (i >= K_REL * E_EDGES) return;
    int k = i / E_EDGES;
    atomicAdd(&cnt[k * N_NODES + rows[i]], 1);
}
__global__ __launch_bounds__(SCT) void scan_part(const int* __restrict__ cnt, int* __restrict__ bsum)
{
    __shared__ int ss[SCT];
    int b = blockIdx.x, t = threadIdx.x;
    int base = b * SCT * SPT + t * SPT;
    int local = 0;
#pragma unroll
    for (int i = 0; i < SPT; i++) {
        int idx = base + i;
        if (idx < NBUCKET) local += cnt[idx];
    }
    ss[t] = local; __syncthreads();
    for (int d = SCT >> 1; d > 0; d >>= 1) {
        if (t < d) ss[t] += ss[t + d];
        __syncthreads();
    }
    if (t == 0) bsum[b] = ss[0];
}
__global__ __launch_bounds__(SCT) void scan_top(const int* __restrict__ bsum,
                                                int* __restrict__ btop, int* __restrict__ off)
{
    __shared__ int ss[SCT];
    int t = threadIdx.x;
    int v = (t < SCB) ? bsum[t] : 0;
    ss[t] = v; __syncthreads();
    for (int d = 1; d < SCT; d <<= 1) {
        int u = (t >= d) ? ss[t - d] : 0;
        __syncthreads();
        ss[t] += u;
        __syncthreads();
    }
    if (t < SCB) btop[t] = ss[t] - v;
    if (t == SCB - 1) off[NBUCKET] = ss[t];
}
__global__ __launch_bounds__(SCT) void scan_write(const int* __restrict__ cnt,
                                                  const int* __restrict__ btop,
                                                  int* __restrict__ off, int* __restrict__ cur)
{
    __shared__ int ss[SCT];
    int b = blockIdx.x, t = threadIdx.x;
    int base = b * SCT * SPT + t * SPT;
    int c[SPT];
    int local = 0;
#pragma unroll
    for (int i = 0; i < SPT; i++) {
        int idx = base + i;
        c[i] = (idx < NBUCKET) ? cnt[idx] : 0;
        local += c[i];
    }
    ss[t] = local; __syncthreads();
    for (int d = 1; d < SCT; d <<= 1) {
        int u = (t >= d) ? ss[t - d] : 0;
        __syncthreads();
        ss[t] += u;
        __syncthreads();
    }
    int run = btop[b] + ss[t] - local;
#pragma unroll
    for (int i = 0; i < SPT; i++) {
        int idx = base + i;
        if (idx < NBUCKET) { off[idx] = run; cur[idx] = run; run += c[i]; }
    }
}
__global__ void fill_kernel(const int* __restrict__ rows, const int* __restrict__ cols,
                            int* __restrict__ cur, int* __restrict__ ecol)
{
    int i = blockIdx.x * blockDim.x + threadIdx.x;
    if (i >= K_REL * E_EDGES) return;
    int k = i / E_EDGES;
    int p = atomicAdd(&cur[k * N_NODES + rows[i]], 1);
    ecol[p] = cols[i];
}

// ================= gather (4-way unrolled for MLP) =================
__global__ void gather_kernel(const int* __restrict__ off, const int* __restrict__ ecol,
                              const float* __restrict__ Z, float* __restrict__ Mb)
{
    int w = (blockIdx.x * blockDim.x + threadIdx.x) >> 5;
    int lane = threadIdx.x & 31;
    if (w >= NBUCKET) return;
    int k = w / N_NODES;
    int n = w - k * N_NODES;
    int s = off[w], t = off[w + 1];
    float4 a0 = make_float4(0.f, 0.f, 0.f, 0.f);
    float4 a1 = make_float4(0.f, 0.f, 0.f, 0.f);
    float4 a2 = make_float4(0.f, 0.f, 0.f, 0.f);
    float4 a3 = make_float4(0.f, 0.f, 0.f, 0.f);
    int e = s;
    for (; e + 4 <= t; e += 4) {
        int c0 = __ldg(ecol + e), c1 = __ldg(ecol + e + 1);
        int c2 = __ldg(ecol + e + 2), c3 = __ldg(ecol + e + 3);
        float4 v0 = __ldg(reinterpret_cast<const float4*>(Z + (size_t)c0 * DDIM) + lane);
        float4 v1 = __ldg(reinterpret_cast<const float4*>(Z + (size_t)c1 * DDIM) + lane);
        float4 v2 = __ldg(reinterpret_cast<const float4*>(Z + (size_t)c2 * DDIM) + lane);
        float4 v3 = __ldg(reinterpret_cast<const float4*>(Z + (size_t)c3 * DDIM) + lane);
        a0.x += v0.x; a0.y += v0.y; a0.z += v0.z; a0.w += v0.w;
        a1.x += v1.x; a1.y += v1.y; a1.z += v1.z; a1.w += v1.w;
        a2.x += v2.x; a2.y += v2.y; a2.z += v2.z; a2.w += v2.w;
        a3.x += v3.x; a3.y += v3.y; a3.z += v3.z; a3.w += v3.w;
    }
    for (; e < t; e++) {
        int c0 = __ldg(ecol + e);
        float4 v0 = __ldg(reinterpret_cast<const float4*>(Z + (size_t)c0 * DDIM) + lane);
        a0.x += v0.x; a0.y += v0.y; a0.z += v0.z; a0.w += v0.w;
    }
    a0.x += a2.x; a0.y += a2.y; a0.z += a2.z; a0.w += a2.w;
    a1.x += a3.x; a1.y += a3.y; a1.z += a3.z; a1.w += a3.w;
    float4 r;
    r.x = fminf(fmaxf(a0.x + a1.x, -MCLAMP), MCLAMP);
    r.y = fminf(fmaxf(a0.y + a1.y, -MCLAMP), MCLAMP);
    r.z = fminf(fmaxf(a0.z + a1.z, -MCLAMP), MCLAMP);
    r.w = fminf(fmaxf(a0.w + a1.w, -MCLAMP), MCLAMP);
    reinterpret_cast<float4*>(Mb + ((size_t)n * K_REL + k) * DDIM)[lane] = r;
}

// ===== fused: softmax + weighted sum + residual (+pairnorm of H input) + stats tail =====
#define FUSE_NPB 16
template <bool HNORM>
__global__ __launch_bounds__(DDIM) void fused_kernel(
    const float* __restrict__ Mb, const float* __restrict__ scores,
    const float* __restrict__ mask,
    const float* __restrict__ Hsrc, const float* __restrict__ hstats,
    float* __restrict__ Xres,
    float* __restrict__ colsum, float* __restrict__ alpha_out,
    int* __restrict__ done, float* __restrict__ stats_out)
{
    int d = threadIdx.x;
    int n0 = blockIdx.x * FUSE_NPB;
    __shared__ float a[FUSE_NPB][K_REL];
    __shared__ float wsum[4];
    __shared__ int slast;
    float hmu = 0.f, hinv = 0.f;
    if (HNORM) { hmu = hstats[d]; hinv = hstats[DDIM]; }
    if (d < FUSE_NPB) {
        int n = n0 + d;
        float s[K_REL], aa[K_REL];
        float m = -1e30f;
#pragma unroll
        for (int k = 0; k < K_REL; k++) { s[k] = scores[n * K_REL + k] * TEMP_INV; m = fmaxf(m, s[k]); }
        float sum = 0.f;
#pragma unroll
        for (int k = 0; k < K_REL; k++) { aa[k] = __expf(s[k] - m); sum += aa[k]; }
        float inv = 1.f / sum;
        float sum2 = 0.f;
#pragma unroll
        for (int k = 0; k < K_REL; k++) { aa[k] = aa[k] * inv * mask[n * K_REL + k]; sum2 += aa[k]; }
        float inv2 = 1.f / fmaxf(sum2, 1e-12f);
        float sum3 = 0.f;
#pragma unroll
        for (int k = 0; k < K_REL; k++) { aa[k] = fmaxf(aa[k] * inv2, 1e-8f); sum3 += aa[k]; }
        float inv3 = 1.f / fmaxf(sum3, 1e-12f);
#pragma unroll
        for (int k = 0; k < K_REL; k++) { aa[k] *= inv3; a[d][k] = aa[k]; }
        *reinterpret_cast<float4*>(alpha_out + (size_t)n * K_REL) =
            make_float4(aa[0], aa[1], aa[2], aa[3]);
    }
    __syncthreads();
    float csum = 0.f, qsum = 0.f;
#pragma unroll
    for (int i = 0; i < FUSE_NPB; i++) {
        int n = n0 + i;
        if (n >= N_NODES) break;
        float f = 0.f;
#pragma unroll
        for (int k = 0; k < K_REL; k++)
            f += a[i][k] * Mb[((size_t)n * K_REL + k) * DDIM + d];
        float h = Hsrc[(size_t)n * DDIM + d];
        if (HNORM) h = fmaxf((h - hmu) * hinv, 0.f);
        float x = f + h;
        Xres[(size_t)n * DDIM + d] = x;
        csum += x;
        qsum += x * x;
    }
    atomicAdd(&colsum[d], csum);
#pragma unroll
    for (int o = 16; o > 0; o >>= 1) qsum += __shfl_xor_sync(0xFFFFFFFFu, qsum, o);
    if ((d & 31) == 0) wsum[d >> 5] = qsum;
    __syncthreads();
    if (d == 0) {
        atomicAdd(&colsum[DDIM], wsum[0] + wsum[1] + wsum[2] + wsum[3]);
        __threadfence();
        slast = (atomicAdd(done, 1) == (int)gridDim.x - 1) ? 1 : 0;
    }
    __syncthreads();
    if (slast) {
        float mu = colsum[d] * (1.0f / N_NODES);
        stats_out[d] = mu;
        float q = mu * mu;
#pragma unroll
        for (int o = 16; o > 0; o >>= 1) q += __shfl_xor_sync(0xFFFFFFFFu, q, o);
        if ((d & 31) == 0) wsum[d >> 5] = q;
        __syncthreads();
        if (d == 0) {
            float summu2 = wsum[0] + wsum[1] + wsum[2] + wsum[3];
            float var = (colsum[DDIM] - (float)N_NODES * summu2) * (1.0f / N_NODES);
            var = fmaxf(var, 0.f);
            stats_out[DDIM] = 1.0f / (sqrtf(var) + 1e-6f);
        }
    }
}

// ================= host =================
extern "C" void kernel_launch(void* const* d_in, const int* in_sizes, int n_in,
                              void* d_out, int out_size)
{
    const float* X      = (const float*)d_in[0];
    const int*   rows   = (const int*)d_in[1];
    const int*   cols   = (const int*)d_in[2];
    const float* mask   = (const float*)d_in[3];
    const float* logdeg = (const float*)d_in[4];
    const float* W_in0  = (const float*)d_in[5];
    const float* b_in0  = (const float*)d_in[6];
    const float* W_in1  = (const float*)d_in[7];
    const float* b_in1  = (const float*)d_in[8];
    const float* W_in2  = (const float*)d_in[9];
    const float* b_in2  = (const float*)d_in[10];
    const float* Wmsg[2]  = {(const float*)d_in[11], (const float*)d_in[16]};
    const float* Wg1[2]   = {(const float*)d_in[12], (const float*)d_in[17]};
    const float* bg1[2]   = {(const float*)d_in[13], (const float*)d_in[18]};
    const float* Wg2[2]   = {(const float*)d_in[14], (const float*)d_in[19]};
    const float* bg2[2]   = {(const float*)d_in[15], (const float*)d_in[20]};
    const float* Wh1    = (const float*)d_in[21];
    const float* bh1    = (const float*)d_in[22];
    const float* Wh2    = (const float*)d_in[23];
    const float* bh2    = (const float*)d_in[24];
    float* out = (float*)d_out;

    float *buf0, *buf1, *H, *Z, *Mb, *gateH, *scores, *Xres, *colsum, *stats;
    int *cnt, *off, *cur, *ecol, *bsum, *btop, *done;
    cudaGetSymbolAddress((void**)&buf0,  g_buf0);
    cudaGetSymbolAddress((void**)&buf1,  g_buf1);
    cudaGetSymbolAddress((void**)&H,     g_H);
    cudaGetSymbolAddress((void**)&Z,     g_Z);
    cudaGetSymbolAddress((void**)&Mb,    g_M);
    cudaGetSymbolAddress((void**)&gateH, g_gateH);
    cudaGetSymbolAddress((void**)&scores,g_scores);
    cudaGetSymbolAddress((void**)&Xres,  g_Xres);
    cudaGetSymbolAddress((void**)&colsum,g_colsum);
    cudaGetSymbolAddress((void**)&stats, g_stats);
    cudaGetSymbolAddress((void**)&done,  g_done);
    cudaGetSymbolAddress((void**)&cnt,   g_cnt);
    cudaGetSymbolAddress((void**)&off,   g_off);
    cudaGetSymbolAddress((void**)&cur,   g_cur);
    cudaGetSymbolAddress((void**)&ecol,  g_ecol);
    cudaGetSymbolAddress((void**)&bsum,  g_bsum);
    cudaGetSymbolAddress((void**)&btop,  g_btop);

    cudaFuncSetAttribute(mma_gemm<true,true,false,false,false,false>,  cudaFuncAttributeMaxDynamicSharedMemorySize, GEMM_SMEM);
    cudaFuncSetAttribute(mma_gemm<false,false,true,false,false,false>, cudaFuncAttributeMaxDynamicSharedMemorySize, GEMM_SMEM);
    cudaFuncSetAttribute(mma_gemm<false,false,true,false,false,true>,  cudaFuncAttributeMaxDynamicSharedMemorySize, GEMM_SMEM);
    cudaFuncSetAttribute(mma_gemm<false,false,false,true,true,false>,  cudaFuncAttributeMaxDynamicSharedMemorySize, GEMM_SMEM);
    cudaFuncSetAttribute(mma_gemm<false,false,false,true,false,true>,  cudaFuncAttributeMaxDynamicSharedMemorySize, GEMM_SMEM);

    const int MT = (N_NODES + 63) / 64;           // 313
    const int MTG = (N_NODES * K_REL + 63) / 64;  // 1250
    const int FUSEB = (N_NODES + FUSE_NPB - 1) / FUSE_NPB;

    // 0-2: CSR front half (+ colsum/done zeroing)
    zero_int_kernel<<<(NBUCKET + 255) / 256, 256>>>(cnt, NBUCKET, (int*)colsum, 2 * SSTRIDE, done);
    hist_kernel<<<(K_REL * E_EDGES + 255) / 256, 256>>>(rows, cnt);
    scan_part<<<SCB, SCT>>>(cnt, bsum);

    // 3 (profiled): encoder GEMM 1
    mma_gemm<true,true,false,false,false,false><<<dim3(2, MT), GT, GEMM_SMEM>>>(
        X, W_in0, b_in0, buf0, N_NODES, INDIM, HINDIM, nullptr, nullptr,
        nullptr, nullptr, nullptr, nullptr, nullptr, nullptr, nullptr);

    // 4-6: CSR back half
    scan_top<<<1, SCT>>>(bsum, btop, off);
    scan_write<<<SCB, SCT>>>(cnt, btop, off, cur);
    fill_kernel<<<(K_REL * E_EDGES + 255) / 256, 256>>>(rows, cols, cur, ecol);

    // 7-8: encoder GEMMs 2-3
    mma_gemm<true,true,false,false,false,false><<<dim3(2, MT), GT, GEMM_SMEM>>>(
        buf0, W_in1, b_in1, buf1, N_NODES, HINDIM, HINDIM, nullptr, nullptr,
        nullptr, nullptr, nullptr, nullptr, nullptr, nullptr, nullptr);
    mma_gemm<true,true,false,false,false,false><<<dim3(1, MT), GT, GEMM_SMEM>>>(
        buf1, W_in2, b_in2, H, N_NODES, HINDIM, DDIM, nullptr, nullptr,
        nullptr, nullptr, nullptr, nullptr, nullptr, nullptr, nullptr);

    // ---- block 0 ----
    mma_gemm<false,false,true,false,false,false><<<dim3(2, MT), GT, GEMM_SMEM>>>(
        H, Wmsg[0], nullptr, Z, N_NODES, DDIM, DDIM, Wg1[0], gateH,
        nullptr, nullptr, nullptr, nullptr, nullptr, nullptr, nullptr);
    gather_kernel<<<(NBUCKET * 32 + 255) / 256, 256>>>(off, ecol, Z, Mb);
    mma_gemm<false,false,false,true,true,false><<<dim3(1, MTG), GT, GEMM_SMEM>>>(
        Mb, Wg1[0] + DDIM * GATEH, nullptr, scores, N_NODES * K_REL, DDIM, GATEH,
        nullptr, nullptr,
        gateH, logdeg, Wg1[0] + 2 * DDIM * GATEH, bg1[0], Wg2[0], bg2[0], nullptr);
    fused_kernel<false><<<FUSEB, DDIM>>>(
        Mb, scores, mask, H, nullptr, Xres, colsum,
        out + N_NODES, done, stats);

    // ---- block 1 (pairnorm folded into consumers) ----
    mma_gemm<false,false,true,false,false,true><<<dim3(2, MT), GT, GEMM_SMEM>>>(
        Xres, Wmsg[1], nullptr, Z, N_NODES, DDIM, DDIM, Wg1[1], gateH,
        nullptr, nullptr, nullptr, nullptr, nullptr, nullptr, stats);
    gather_kernel<<<(NBUCKET * 32 + 255) / 256, 256>>>(off, ecol, Z, Mb);
    mma_gemm<false,false,false,true,true,false><<<dim3(1, MTG), GT, GEMM_SMEM>>>(
        Mb, Wg1[1] + DDIM * GATEH, nullptr, scores, N_NODES * K_REL, DDIM, GATEH,
        nullptr, nullptr,
        gateH, logdeg, Wg1[1] + 2 * DDIM * GATEH, bg1[1], Wg2[1], bg2[1], nullptr);
    fused_kernel<true><<<FUSEB, DDIM>>>(
        Mb, scores, mask, Xres, stats, Xres, colsum + SSTRIDE,
        out + N_NODES + (size_t)N_NODES * K_REL, done + 1, stats + SSTRIDE);

    // ---- head ----
    mma_gemm<false,false,false,true,false,true><<<dim3(1, MT), GT, GEMM_SMEM>>>(
        Xres, Wh1, nullptr, out, N_NODES, DDIM, DDIM, nullptr, nullptr,
        nullptr, nullptr, nullptr, bh1, Wh2, bh2, stats + SSTRIDE);
}

// round 17
// speedup vs baseline: 1.0469x; 1.0060x over previous
#include <cuda_runtime.h>
#include <cuda_bf16.h>
#include <math.h>
#include <cstdint>

#define N_NODES 20000
#define K_REL   4
#define E_EDGES 320000
#define INDIM   1024
#define HINDIM  256
#define DDIM    128
#define GATEH   128
#define TEMP_INV (1.0f/0.6f)
#define MCLAMP  20.0f
#define NBUCKET (K_REL * N_NODES)
#define SSTRIDE 132
#define WG1ROWS (2 * DDIM + 1)

// ---------------- scratch ----------------
__device__ float g_buf0[N_NODES * HINDIM];
__device__ float g_buf1[N_NODES * HINDIM];
__device__ float g_H[N_NODES * DDIM];
__device__ float g_Z[N_NODES * DDIM];
__device__ float g_M[N_NODES * K_REL * DDIM];
__device__ float g_gateH[N_NODES * GATEH];
__device__ float g_scores[N_NODES * K_REL];
__device__ float g_Xres[N_NODES * DDIM];
__device__ __align__(16) float g_colsum[2 * SSTRIDE];
__device__ __align__(16) float g_stats[2 * SSTRIDE];
__device__ int   g_done[2];
// weight bf16 hi/lo planes
__device__ __align__(16) __nv_bfloat16 g_W0h[INDIM * HINDIM];
__device__ __align__(16) __nv_bfloat16 g_W0l[INDIM * HINDIM];
__device__ __align__(16) __nv_bfloat16 g_W1h[HINDIM * HINDIM];
__device__ __align__(16) __nv_bfloat16 g_W1l[HINDIM * HINDIM];
__device__ __align__(16) __nv_bfloat16 g_W2h[HINDIM * DDIM];
__device__ __align__(16) __nv_bfloat16 g_W2l[HINDIM * DDIM];
__device__ __align__(16) __nv_bfloat16 g_Wmh[2][DDIM * DDIM];
__device__ __align__(16) __nv_bfloat16 g_Wml[2][DDIM * DDIM];
__device__ __align__(16) __nv_bfloat16 g_Wg1h[2][WG1ROWS * GATEH];
__device__ __align__(16) __nv_bfloat16 g_Wg1l[2][WG1ROWS * GATEH];
__device__ __align__(16) __nv_bfloat16 g_Wh1h[DDIM * DDIM];
__device__ __align__(16) __nv_bfloat16 g_Wh1l[DDIM * DDIM];
// CSR
__device__ int g_cnt[NBUCKET];
__device__ int g_off[NBUCKET + 1];
__device__ int g_cur[NBUCKET];
__device__ int g_ecol[K_REL * E_EDGES];
__device__ int g_bsum[256];
__device__ int g_btop[256];

// ================= helpers =================
__device__ __forceinline__ uint32_t smem_u32(const void* p) {
    uint32_t a;
    asm("{ .reg .u64 t; cvta.to.shared.u64 t, %1; cvt.u32.u64 %0, t; }" : "=r"(a) : "l"(p));
    return a;
}
__device__ __forceinline__ void ldsm_x4(uint32_t* r, uint32_t addr) {
    asm volatile("ldmatrix.sync.aligned.m8n8.x4.shared.b16 {%0,%1,%2,%3}, [%4];"
        : "=r"(r[0]), "=r"(r[1]), "=r"(r[2]), "=r"(r[3]) : "r"(addr));
}
__device__ __forceinline__ void ldsm_x4_t(uint32_t* r, uint32_t addr) {
    asm volatile("ldmatrix.sync.aligned.m8n8.x4.trans.shared.b16 {%0,%1,%2,%3}, [%4];"
        : "=r"(r[0]), "=r"(r[1]), "=r"(r[2]), "=r"(r[3]) : "r"(addr));
}
__device__ __forceinline__ void mma_bf16(float* c, const uint32_t* a, const uint32_t* b) {
    asm volatile("mma.sync.aligned.m16n8k16.row.col.f32.bf16.bf16.f32 "
        "{%0,%1,%2,%3}, {%4,%5,%6,%7}, {%8,%9}, {%0,%1,%2,%3};"
        : "+f"(c[0]), "+f"(c[1]), "+f"(c[2]), "+f"(c[3])
        : "r"(a[0]), "r"(a[1]), "r"(a[2]), "r"(a[3]), "r"(b[0]), "r"(b[1]));
}
__device__ __forceinline__ uint32_t pack2(float a, float b) {
    __nv_bfloat162 h = __floats2bfloat162_rn(a, b);
    return *reinterpret_cast<uint32_t*>(&h);
}
#define CP16(dst, src) \
    asm volatile("cp.async.cg.shared.global [%0], [%1], 16;" \
        :: "r"(dst), "l"(src) : "memory")
#define CP_COMMIT() asm volatile("cp.async.commit_group;" ::: "memory")
#define CP_WAIT0()  asm volatile("cp.async.wait_group 0;" ::: "memory")

// ================= bf16 3-split GEMM, pre-split weights: BM=64, BN=128 =================
#define GT 256
#define ROWB_A 80
#define ROWB_B 272
#define A_TILE (64 * ROWB_A)
#define B_TILE (32 * ROWB_B)
#define STAGE_B (2 * A_TILE + 2 * B_TILE)   // 27648
#define GEMM_SMEM (2 * STAGE_B)             // 55296
#define B_OFF (2 * A_TILE)

template <bool RELU, bool BIAS, bool DUAL, bool REDUCE, bool GHLD, bool ANORM>
__global__ __launch_bounds__(GT, 2) void mma_gemm(
    const float* __restrict__ A,
    const __nv_bfloat16* __restrict__ B1h, const __nv_bfloat16* __restrict__ B1l,
    const float* __restrict__ bias, float* __restrict__ C1,
    int M, int K, int N,
    const __nv_bfloat16* __restrict__ B2h, const __nv_bfloat16* __restrict__ B2l,
    float* __restrict__ C2,
    const float* __restrict__ gh, const float* __restrict__ ldg_,
    const float* __restrict__ wld, const float* __restrict__ rb1,
    const float* __restrict__ rb2, const float* __restrict__ rb3,
    const float* __restrict__ anorm_stats)
{
    extern __shared__ __align__(128) char smem[];
    const int tid = threadIdx.x;
    const int lane = tid & 31;
    const int wid = tid >> 5;
    const int warp_m = wid & 1;
    const int warp_n = wid >> 1;
    const int rowBase = blockIdx.y * 64;
    const int nch = K >> 5;

    const __nv_bfloat16* Bph = B1h;
    const __nv_bfloat16* Bpl = B1l;
    float* Cp = C1;
    int cb = blockIdx.x * 128;
    if (DUAL) {
        if (blockIdx.x == 1) { Bph = B2h; Bpl = B2l; Cp = C2; }
        cb = 0;
    }

    float anorm_inv = 0.f;
    if (ANORM) anorm_inv = __ldg(anorm_stats + DDIM);

    float acc[2][4][4];
#pragma unroll
    for (int i = 0; i < 2; i++)
#pragma unroll
        for (int j = 0; j < 4; j++)
#pragma unroll
            for (int q = 0; q < 4; q++) acc[i][j][q] = 0.f;

    const uint32_t sb = smem_u32(smem);
    const int aRow = warp_m * 32 + (lane & 7) + ((lane >> 3) & 1) * 8;
    const int aK   = ((lane >> 4) & 1) * 8;
    const uint32_t aBase = sb + (uint32_t)(aRow * ROWB_A + aK * 2);
    const uint32_t bBase = sb + (uint32_t)B_OFF
                         + (uint32_t)((lane & 15) * ROWB_B + (lane >> 4) * 16);

    // per-thread cp.async coords for B (32 rows x 16 segs per plane; 2 per thread)
    const int br0  = tid >> 4;          // 0..15
    const int bseg = tid & 15;          // 0..15
    const uint32_t dB0 = (uint32_t)(B_OFF + br0 * ROWB_B + bseg * 16);
    const uint32_t dB1 = (uint32_t)(B_OFF + (br0 + 16) * ROWB_B + bseg * 16);

    float4 aR[2];

    auto issueB = [&](int c, int s) {
        const uint32_t st = sb + (uint32_t)(s * STAGE_B);
        const size_t base0 = (size_t)(c * 32 + br0) * N + cb + bseg * 8;
        const size_t base1 = base0 + (size_t)16 * N;
        CP16(st + dB0,          Bph + base0);
        CP16(st + dB0 + B_TILE, Bpl + base0);
        CP16(st + dB1,          Bph + base1);
        CP16(st + dB1 + B_TILE, Bpl + base1);
    };
    auto gloadA = [&](int c) {
        const int k0 = c << 5;
#pragma unroll
        for (int j = 0; j < 2; j++) {
            int idx = tid + j * GT;
            int r = idx >> 3;
            int col = (idx & 7) * 4;
            int gr = rowBase + r;
            float4 v = make_float4(0.f, 0.f, 0.f, 0.f);
            if (gr < M) {
                v = *reinterpret_cast<const float4*>(A + (size_t)gr * K + k0 + col);
                if (ANORM) {
                    float4 mu = *reinterpret_cast<const float4*>(anorm_stats + k0 + col);
                    v.x = fmaxf((v.x - mu.x) * anorm_inv, 0.f);
                    v.y = fmaxf((v.y - mu.y) * anorm_inv, 0.f);
                    v.z = fmaxf((v.z - mu.z) * anorm_inv, 0.f);
                    v.w = fmaxf((v.w - mu.w) * anorm_inv, 0.f);
                }
            }
            aR[j] = v;
        }
    };
    auto sstoreA = [&](int s) {
        char* st = smem + s * STAGE_B;
#pragma unroll
        for (int j = 0; j < 2; j++) {
            int idx = tid + j * GT;
            int r = idx >> 3;
            int col = (idx & 7) * 4;
            int offA = r * ROWB_A + col * 2;
            float4 v = aR[j];
            float hx = __bfloat162float(__float2bfloat16(v.x));
            float hy = __bfloat162float(__float2bfloat16(v.y));
            float hz = __bfloat162float(__float2bfloat16(v.z));
            float hw = __bfloat162float(__float2bfloat16(v.w));
            *reinterpret_cast<uint2*>(st + offA) =
                make_uint2(pack2(hx, hy), pack2(hz, hw));
            *reinterpret_cast<uint2*>(st + A_TILE + offA) =
                make_uint2(pack2(v.x - hx, v.y - hy), pack2(v.z - hz, v.w - hw));
        }
    };

    issueB(0, 0); CP_COMMIT();
    gloadA(0);
    sstoreA(0);
    CP_WAIT0();
    __syncthreads();

    for (int c = 0; c < nch; c++) {
        const uint32_t stoff = (uint32_t)((c & 1) * STAGE_B);
        if (c + 1 < nch) {
            issueB(c + 1, (c + 1) & 1); CP_COMMIT();
            gloadA(c + 1);
        }

#pragma unroll
        for (int ks = 0; ks < 2; ks++) {
            uint32_t ah[2][4], al[2][4];
#pragma unroll
            for (int mt = 0; mt < 2; mt++) {
                ldsm_x4(ah[mt], aBase + stoff + mt * 16 * ROWB_A + ks * 32);
                ldsm_x4(al[mt], aBase + stoff + A_TILE + mt * 16 * ROWB_A + ks * 32);
            }
#pragma unroll
            for (int nq = 0; nq < 2; nq++) {
                uint32_t bh[4], bl[4];
                uint32_t ad = bBase + stoff + ks * 16 * ROWB_B
                            + (uint32_t)((warp_n * 32 + nq * 16) * 2);
                ldsm_x4_t(bh, ad);
                ldsm_x4_t(bl, ad + B_TILE);
#pragma unroll
                for (int mt = 0; mt < 2; mt++) {
#pragma unroll
                    for (int half = 0; half < 2; half++) {
                        int nt = nq * 2 + half;
                        mma_bf16(acc[mt][nt], ah[mt], &bh[half * 2]);
                        mma_bf16(acc[mt][nt], ah[mt], &bl[half * 2]);
                        mma_bf16(acc[mt][nt], al[mt], &bh[half * 2]);
                    }
                }
            }
        }
        if (c + 1 < nch) sstoreA((c + 1) & 1);
        CP_WAIT0();
        __syncthreads();
    }

    const int g = lane >> 2;
    const int tc2 = (lane & 3) * 2;

    if (REDUCE) {
        float* sred = reinterpret_cast<float*>(smem);
        float part[2][2] = {{0.f, 0.f}, {0.f, 0.f}};
#pragma unroll
        for (int mt = 0; mt < 2; mt++) {
#pragma unroll
            for (int nt = 0; nt < 4; nt++) {
                int col = warp_n * 32 + nt * 8 + tc2;
                float w0 = __ldg(rb2 + col), w1 = __ldg(rb2 + col + 1);
                float b0 = __ldg(rb1 + col), b1 = __ldg(rb1 + col + 1);
                float wl0 = 0.f, wl1 = 0.f;
                if (GHLD) { wl0 = __ldg(wld + col); wl1 = __ldg(wld + col + 1); }
#pragma unroll
                for (int h = 0; h < 2; h++) {
                    int row = rowBase + warp_m * 32 + mt * 16 + h * 8 + g;
                    float v0 = acc[mt][nt][h * 2 + 0] + b0;
                    float v1 = acc[mt][nt][h * 2 + 1] + b1;
                    if (GHLD) {
                        int n = row >> 2;
                        float ldv = __ldg(ldg_ + row);
                        v0 += gh[(size_t)n * GATEH + col]     + ldv * wl0;
                        v1 += gh[(size_t)n * GATEH + col + 1] + ldv * wl1;
                    }
                    v0 = fmaxf(v0, 0.f); v1 = fmaxf(v1, 0.f);
                    part[mt][h] += v0 * w0 + v1 * w1;
                }
            }
        }
#pragma unroll
        for (int mt = 0; mt < 2; mt++)
#pragma unroll
            for (int h = 0; h < 2; h++) {
                float p = part[mt][h];
                p += __shfl_xor_sync(0xFFFFFFFFu, p, 1);
                p += __shfl_xor_sync(0xFFFFFFFFu, p, 2);
                if ((lane & 3) == 0)
                    sred[(warp_m * 32 + mt * 16 + h * 8 + g) * 4 + warp_n] = p;
            }
        __syncthreads();
        if (tid < 64) {
            int row = rowBase + tid;
            if (row < M) {
                float sv = sred[tid * 4] + sred[tid * 4 + 1]
                         + sred[tid * 4 + 2] + sred[tid * 4 + 3] + __ldg(rb3);
                C1[row] = sv;
            }
        }
        return;
    }

#pragma unroll
    for (int mt = 0; mt < 2; mt++) {
#pragma unroll
        for (int nt = 0; nt < 4; nt++) {
            int row0 = rowBase + warp_m * 32 + mt * 16 + g;
            int col = cb + warp_n * 32 + nt * 8 + tc2;
            float c0 = acc[mt][nt][0], c1 = acc[mt][nt][1];
            float c2 = acc[mt][nt][2], c3 = acc[mt][nt][3];
            if (BIAS) {
                float2 bb = *reinterpret_cast<const float2*>(bias + col);
                c0 += bb.x; c1 += bb.y; c2 += bb.x; c3 += bb.y;
            }
            if (RELU) {
                c0 = fmaxf(c0, 0.f); c1 = fmaxf(c1, 0.f);
                c2 = fmaxf(c2, 0.f); c3 = fmaxf(c3, 0.f);
            }
            if (row0 < M)
                *reinterpret_cast<float2*>(Cp + (size_t)row0 * N + col) = make_float2(c0, c1);
            if (row0 + 8 < M)
                *reinterpret_cast<float2*>(Cp + (size_t)(row0 + 8) * N + col) = make_float2(c2, c3);
        }
    }
}

// ================= batched weight split =================
struct SJob { const float* src; __nv_bfloat16* hi; __nv_bfloat16* lo; int n; };
struct SJobs { SJob j[8]; };

__global__ void split_multi(SJobs jobs)
{
    SJob jb = jobs.j[blockIdx.y];
    int stride = gridDim.x * blockDim.x * 2;
    for (int i = (blockIdx.x * blockDim.x + threadIdx.x) * 2; i < jb.n; i += stride) {
        float2 v = *reinterpret_cast<const float2*>(jb.src + i);
        float h0 = __bfloat162float(__float2bfloat16(v.x));
        float h1 = __bfloat162float(__float2bfloat16(v.y));
        *reinterpret_cast<uint32_t*>(jb.hi + i) = pack2(h0, h1);
        *reinterpret_cast<uint32_t*>(jb.lo + i) = pack2(v.x - h0, v.y - h1);
    }
}

// ================= CSR build =================
#define SCB 160
#define SCT 256
#define SPT 2

__global__ void zero_int_kernel(int* p, int n, int* q, int m, int* dn) {
    int i = blockIdx.x * blockDim.x + threadIdx.x;
    if (i < n) p[i] = 0;
    if (i < m) q[i] = 0;
    if (i < 2) dn[i] = 0;
}
__global__ void hist_kernel(const int* __restrict__ rows, int* __restrict__ cnt) {
    int i = blockIdx.x * blockDim.x + threadIdx.x;
    if (i >= K_REL * E_EDGES) return;
    int k = i / E_EDGES;
    atomicAdd(&cnt[k * N_NODES + rows[i]], 1);
}
__global__ __launch_bounds__(SCT) void scan_part(const int* __restrict__ cnt, int* __restrict__ bsum)
{
    __shared__ int ss[SCT];
    int b = blockIdx.x, t = threadIdx.x;
    int base = b * SCT * SPT + t * SPT;
    int local = 0;
#pragma unroll
    for (int i = 0; i < SPT; i++) {
        int idx = base + i;
        if (idx < NBUCKET) local += cnt[idx];
    }
    ss[t] = local; __syncthreads();
    for (int d = SCT >> 1; d > 0; d >>= 1) {
        if (t < d) ss[t] += ss[t + d];
        __syncthreads();
    }
    if (t == 0) bsum[b] = ss[0];
}
__global__ __launch_bounds__(SCT) void scan_top(const int* __restrict__ bsum,
                                                int* __restrict__ btop, int* __restrict__ off)
{
    __shared__ int ss[SCT];
    int t = threadIdx.x;
    int v = (t < SCB) ? bsum[t] : 0;
    ss[t] = v; __syncthreads();
    for (int d = 1; d < SCT; d <<= 1) {
        int u = (t >= d) ? ss[t - d] : 0;
        __syncthreads();
        ss[t] += u;
        __syncthreads();
    }
    if (t < SCB) btop[t] = ss[t] - v;
    if (t == SCB - 1) off[NBUCKET] = ss[t];
}
__global__ __launch_bounds__(SCT) void scan_write(const int* __restrict__ cnt,
                                                  const int* __restrict__ btop,
                                                  int* __restrict__ off, int* __restrict__ cur)
{
    __shared__ int ss[SCT];
    int b = blockIdx.x, t = threadIdx.x;
    int base = b * SCT * SPT + t * SPT;
    int c[SPT];
    int local = 0;
#pragma unroll
    for (int i = 0; i < SPT; i++) {
        int idx = base + i;
        c[i] = (idx < NBUCKET) ? cnt[idx] : 0;
        local += c[i];
    }
    ss[t] = local; __syncthreads();
    for (int d = 1; d < SCT; d <<= 1) {
        int u = (t >= d) ? ss[t - d] : 0;
        __syncthreads();
        ss[t] += u;
        __syncthreads();
    }
    int run = btop[b] + ss[t] - local;
#pragma unroll
    for (int i = 0; i < SPT; i++) {
        int idx = base + i;
        if (idx < NBUCKET) { off[idx] = run; cur[idx] = run; run += c[i]; }
    }
}
__global__ void fill_kernel(const int* __restrict__ rows, const int* __restrict__ cols,
                            int* __restrict__ cur, int* __restrict__ ecol)
{
    int i = blockIdx.x * blockDim.x + threadIdx.x;
    if (i >= K_REL * E_EDGES) return;
    int k = i / E_EDGES;
    int p = atomicAdd(&cur[k * N_NODES + rows[i]], 1);
    ecol[p] = cols[i];
}

// ================= gather =================
__global__ void gather_kernel(const int* __restrict__ off, const int* __restrict__ ecol,
                              const float* __restrict__ Z, float* __restrict__ Mb)
{
    int w = (blockIdx.x * blockDim.x + threadIdx.x) >> 5;
    int lane = threadIdx.x & 31;
    if (w >= NBUCKET) return;
    int k = w / N_NODES;
    int n = w - k * N_NODES;
    int s = off[w], t = off[w + 1];
    float4 a0 = make_float4(0.f, 0.f, 0.f, 0.f);
    float4 a1 = make_float4(0.f, 0.f, 0.f, 0.f);
    float4 a2 = make_float4(0.f, 0.f, 0.f, 0.f);
    float4 a3 = make_float4(0.f, 0.f, 0.f, 0.f);
    int e = s;
    for (; e + 4 <= t; e += 4) {
        int c0 = __ldg(ecol + e), c1 = __ldg(ecol + e + 1);
        int c2 = __ldg(ecol + e + 2), c3 = __ldg(ecol + e + 3);
        float4 v0 = __ldg(reinterpret_cast<const float4*>(Z + (size_t)c0 * DDIM) + lane);
        float4 v1 = __ldg(reinterpret_cast<const float4*>(Z + (size_t)c1 * DDIM) + lane);
        float4 v2 = __ldg(reinterpret_cast<const float4*>(Z + (size_t)c2 * DDIM) + lane);
        float4 v3 = __ldg(reinterpret_cast<const float4*>(Z + (size_t)c3 * DDIM) + lane);
        a0.x += v0.x; a0.y += v0.y; a0.z += v0.z; a0.w += v0.w;
        a1.x += v1.x; a1.y += v1.y; a1.z += v1.z; a1.w += v1.w;
        a2.x += v2.x; a2.y += v2.y; a2.z += v2.z; a2.w += v2.w;
        a3.x += v3.x; a3.y += v3.y; a3.z += v3.z; a3.w += v3.w;
    }
    for (; e < t; e++) {
        int c0 = __ldg(ecol + e);
        float4 v0 = __ldg(reinterpret_cast<const float4*>(Z + (size_t)c0 * DDIM) + lane);
        a0.x += v0.x; a0.y += v0.y; a0.z += v0.z; a0.w += v0.w;
    }
    a0.x += a2.x; a0.y += a2.y; a0.z += a2.z; a0.w += a2.w;
    a1.x += a3.x; a1.y += a3.y; a1.z += a3.z; a1.w += a3.w;
    float4 r;
    r.x = fminf(fmaxf(a0.x + a1.x, -MCLAMP), MCLAMP);
    r.y = fminf(fmaxf(a0.y + a1.y, -MCLAMP), MCLAMP);
    r.z = fminf(fmaxf(a0.z + a1.z, -MCLAMP), MCLAMP);
    r.w = fminf(fmaxf(a0.w + a1.w, -MCLAMP), MCLAMP);
    reinterpret_cast<float4*>(Mb + ((size_t)n * K_REL + k) * DDIM)[lane] = r;
}

// ===== fused: softmax + weighted sum + residual (+pairnorm of H input) + stats tail =====
#define FUSE_NPB 16
template <bool HNORM>
__global__ __launch_bounds__(DDIM) void fused_kernel(
    const float* __restrict__ Mb, const float* __restrict__ scores,
    const float* __restrict__ mask,
    const float* __restrict__ Hsrc, const float* __restrict__ hstats,
    float* __restrict__ Xres,
    float* __restrict__ colsum, float* __restrict__ alpha_out,
    int* __restrict__ done, float* __restrict__ stats_out)
{
    int d = threadIdx.x;
    int n0 = blockIdx.x * FUSE_NPB;
    __shared__ float a[FUSE_NPB][K_REL];
    __shared__ float wsum[4];
    __shared__ int slast;
    float hmu = 0.f, hinv = 0.f;
    if (HNORM) { hmu = hstats[d]; hinv = hstats[DDIM]; }
    if (d < FUSE_NPB) {
        int n = n0 + d;
        float s[K_REL], aa[K_REL];
        float m = -1e30f;
#pragma unroll
        for (int k = 0; k < K_REL; k++) { s[k] = scores[n * K_REL + k] * TEMP_INV; m = fmaxf(m, s[k]); }
        float sum = 0.f;
#pragma unroll
        for (int k = 0; k < K_REL; k++) { aa[k] = __expf(s[k] - m); sum += aa[k]; }
        float inv = 1.f / sum;
        float sum2 = 0.f;
#pragma unroll
        for (int k = 0; k < K_REL; k++) { aa[k] = aa[k] * inv * mask[n * K_REL + k]; sum2 += aa[k]; }
        float inv2 = 1.f / fmaxf(sum2, 1e-12f);
        float sum3 = 0.f;
#pragma unroll
        for (int k = 0; k < K_REL; k++) { aa[k] = fmaxf(aa[k] * inv2, 1e-8f); sum3 += aa[k]; }
        float inv3 = 1.f / fmaxf(sum3, 1e-12f);
#pragma unroll
        for (int k = 0; k < K_REL; k++) { aa[k] *= inv3; a[d][k] = aa[k]; }
        *reinterpret_cast<float4*>(alpha_out + (size_t)n * K_REL) =
            make_float4(aa[0], aa[1], aa[2], aa[3]);
    }
    __syncthreads();
    float csum = 0.f, qsum = 0.f;
#pragma unroll
    for (int i = 0; i < FUSE_NPB; i++) {
        int n = n0 + i;
        if (n >= N_NODES) break;
        float f = 0.f;
#pragma unroll
        for (int k = 0; k < K_REL; k++)
            f += a[i][k] * Mb[((size_t)n * K_REL + k) * DDIM + d];
        float h = Hsrc[(size_t)n * DDIM + d];
        if (HNORM) h = fmaxf((h - hmu) * hinv, 0.f);
        float x = f + h;
        Xres[(size_t)n * DDIM + d] = x;
        csum += x;
        qsum += x * x;
    }
    atomicAdd(&colsum[d], csum);
#pragma unroll
    for (int o = 16; o > 0; o >>= 1) qsum += __shfl_xor_sync(0xFFFFFFFFu, qsum, o);
    if ((d & 31) == 0) wsum[d >> 5] = qsum;
    __syncthreads();
    if (d == 0) {
        atomicAdd(&colsum[DDIM], wsum[0] + wsum[1] + wsum[2] + wsum[3]);
        __threadfence();
        slast = (atomicAdd(done, 1) == (int)gridDim.x - 1) ? 1 : 0;
    }
    __syncthreads();
    if (slast) {
        float mu = colsum[d] * (1.0f / N_NODES);
        stats_out[d] = mu;
        float q = mu * mu;
#pragma unroll
        for (int o = 16; o > 0; o >>= 1) q += __shfl_xor_sync(0xFFFFFFFFu, q, o);
        if ((d & 31) == 0) wsum[d >> 5] = q;
        __syncthreads();
        if (d == 0) {
            float summu2 = wsum[0] + wsum[1] + wsum[2] + wsum[3];
            float var = (colsum[DDIM] - (float)N_NODES * summu2) * (1.0f / N_NODES);
            var = fmaxf(var, 0.f);
            stats_out[DDIM] = 1.0f / (sqrtf(var) + 1e-6f);
        }
    }
}

// ================= host =================
extern "C" void kernel_launch(void* const* d_in, const int* in_sizes, int n_in,
                              void* d_out, int out_size)
{
    const float* X      = (const float*)d_in[0];
    const int*   rows   = (const int*)d_in[1];
    const int*   cols   = (const int*)d_in[2];
    const float* mask   = (const float*)d_in[3];
    const float* logdeg = (const float*)d_in[4];
    const float* W_in0  = (const float*)d_in[5];
    const float* b_in0  = (const float*)d_in[6];
    const float* W_in1  = (const float*)d_in[7];
    const float* b_in1  = (const float*)d_in[8];
    const float* W_in2  = (const float*)d_in[9];
    const float* b_in2  = (const float*)d_in[10];
    const float* Wmsg[2]  = {(const float*)d_in[11], (const float*)d_in[16]};
    const float* Wg1[2]   = {(const float*)d_in[12], (const float*)d_in[17]};
    const float* bg1[2]   = {(const float*)d_in[13], (const float*)d_in[18]};
    const float* Wg2[2]   = {(const float*)d_in[14], (const float*)d_in[19]};
    const float* bg2[2]   = {(const float*)d_in[15], (const float*)d_in[20]};
    const float* Wh1    = (const float*)d_in[21];
    const float* bh1    = (const float*)d_in[22];
    const float* Wh2    = (const float*)d_in[23];
    const float* bh2    = (const float*)d_in[24];
    float* out = (float*)d_out;

    float *buf0, *buf1, *H, *Z, *Mb, *gateH, *scores, *Xres, *colsum, *stats;
    int *cnt, *off, *cur, *ecol, *bsum, *btop, *done;
    __nv_bfloat16 *W0h, *W0l, *W1h, *W1l, *W2h, *W2l, *Wmh, *Wml, *Wg1h, *Wg1l, *Wh1h, *Wh1l;
    cudaGetSymbolAddress((void**)&buf0,  g_buf0);
    cudaGetSymbolAddress((void**)&buf1,  g_buf1);
    cudaGetSymbolAddress((void**)&H,     g_H);
    cudaGetSymbolAddress((void**)&Z,     g_Z);
    cudaGetSymbolAddress((void**)&Mb,    g_M);
    cudaGetSymbolAddress((void**)&gateH, g_gateH);
    cudaGetSymbolAddress((void**)&scores,g_scores);
    cudaGetSymbolAddress((void**)&Xres,  g_Xres);
    cudaGetSymbolAddress((void**)&colsum,g_colsum);
    cudaGetSymbolAddress((void**)&stats, g_stats);
    cudaGetSymbolAddress((void**)&done,  g_done);
    cudaGetSymbolAddress((void**)&cnt,   g_cnt);
    cudaGetSymbolAddress((void**)&off,   g_off);
    cudaGetSymbolAddress((void**)&cur,   g_cur);
    cudaGetSymbolAddress((void**)&ecol,  g_ecol);
    cudaGetSymbolAddress((void**)&bsum,  g_bsum);
    cudaGetSymbolAddress((void**)&btop,  g_btop);
    cudaGetSymbolAddress((void**)&W0h, g_W0h); cudaGetSymbolAddress((void**)&W0l, g_W0l);
    cudaGetSymbolAddress((void**)&W1h, g_W1h); cudaGetSymbolAddress((void**)&W1l, g_W1l);
    cudaGetSymbolAddress((void**)&W2h, g_W2h); cudaGetSymbolAddress((void**)&W2l, g_W2l);
    cudaGetSymbolAddress((void**)&Wmh, g_Wmh); cudaGetSymbolAddress((void**)&Wml, g_Wml);
    cudaGetSymbolAddress((void**)&Wg1h, g_Wg1h); cudaGetSymbolAddress((void**)&Wg1l, g_Wg1l);
    cudaGetSymbolAddress((void**)&Wh1h, g_Wh1h); cudaGetSymbolAddress((void**)&Wh1l, g_Wh1l);

    cudaFuncSetAttribute(mma_gemm<true,true,false,false,false,false>,  cudaFuncAttributeMaxDynamicSharedMemorySize, GEMM_SMEM);
    cudaFuncSetAttribute(mma_gemm<false,false,true,false,false,false>, cudaFuncAttributeMaxDynamicSharedMemorySize, GEMM_SMEM);
    cudaFuncSetAttribute(mma_gemm<false,false,true,false,false,true>,  cudaFuncAttributeMaxDynamicSharedMemorySize, GEMM_SMEM);
    cudaFuncSetAttribute(mma_gemm<false,false,false,true,true,false>,  cudaFuncAttributeMaxDynamicSharedMemorySize, GEMM_SMEM);
    cudaFuncSetAttribute(mma_gemm<false,false,false,true,false,true>,  cudaFuncAttributeMaxDynamicSharedMemorySize, GEMM_SMEM);

    const int MT = (N_NODES + 63) / 64;           // 313
    const int MTG = (N_NODES * K_REL + 63) / 64;  // 1250
    const int FUSEB = (N_NODES + FUSE_NPB - 1) / FUSE_NPB;

    SJobs sj;
    sj.j[0] = { W_in0,   W0h, W0l, INDIM * HINDIM };
    sj.j[1] = { W_in1,   W1h, W1l, HINDIM * HINDIM };
    sj.j[2] = { W_in2,   W2h, W2l, HINDIM * DDIM };
    sj.j[3] = { Wmsg[0], Wmh,               Wml,               DDIM * DDIM };
    sj.j[4] = { Wmsg[1], Wmh + DDIM * DDIM, Wml + DDIM * DDIM, DDIM * DDIM };
    sj.j[5] = { Wg1[0],  Wg1h,                  Wg1l,                  WG1ROWS * GATEH - 1 };
    sj.j[6] = { Wg1[1],  Wg1h + WG1ROWS * GATEH, Wg1l + WG1ROWS * GATEH, WG1ROWS * GATEH - 1 };
    sj.j[7] = { Wh1,     Wh1h, Wh1l, DDIM * DDIM };
    // note: Wg1 jobs split first 2*128*128 rows (+127 of the wld row; harmless extra)

    // 0-2: split + CSR front
    split_multi<<<dim3(64, 8), 256>>>(sj);
    zero_int_kernel<<<(NBUCKET + 255) / 256, 256>>>(cnt, NBUCKET, (int*)colsum, 2 * SSTRIDE, done);
    hist_kernel<<<(K_REL * E_EDGES + 255) / 256, 256>>>(rows, cnt);

    // 3 (profiled): encoder GEMM 1
    mma_gemm<true,true,false,false,false,false><<<dim3(2, MT), GT, GEMM_SMEM>>>(
        X, W0h, W0l, b_in0, buf0, N_NODES, INDIM, HINDIM,
        nullptr, nullptr, nullptr,
        nullptr, nullptr, nullptr, nullptr, nullptr, nullptr, nullptr);

    // 4-7: CSR back half
    scan_part<<<SCB, SCT>>>(cnt, bsum);
    scan_top<<<1, SCT>>>(bsum, btop, off);
    scan_write<<<SCB, SCT>>>(cnt, btop, off, cur);
    fill_kernel<<<(K_REL * E_EDGES + 255) / 256, 256>>>(rows, cols, cur, ecol);

    // encoder GEMMs 2-3
    mma_gemm<true,true,false,false,false,false><<<dim3(2, MT), GT, GEMM_SMEM>>>(
        buf0, W1h, W1l, b_in1, buf1, N_NODES, HINDIM, HINDIM,
        nullptr, nullptr, nullptr,
        nullptr, nullptr, nullptr, nullptr, nullptr, nullptr, nullptr);
    mma_gemm<true,true,false,false,false,false><<<dim3(1, MT), GT, GEMM_SMEM>>>(
        buf1, W2h, W2l, b_in2, H, N_NODES, HINDIM, DDIM,
        nullptr, nullptr, nullptr,
        nullptr, nullptr, nullptr, nullptr, nullptr, nullptr, nullptr);

    for (int b = 0; b < 2; b++) {
        const __nv_bfloat16* wg1h = Wg1h + (size_t)b * WG1ROWS * GATEH;
        const __nv_bfloat16* wg1l = Wg1l + (size_t)b * WG1ROWS * GATEH;
        const float* astats = (b == 0) ? nullptr : stats;
        const float* Asrc = (b == 0) ? H : Xres;
        if (b == 0)
            mma_gemm<false,false,true,false,false,false><<<dim3(2, MT), GT, GEMM_SMEM>>>(
                Asrc, Wmh + b * DDIM * DDIM, Wml + b * DDIM * DDIM, nullptr, Z,
                N_NODES, DDIM, DDIM, wg1h, wg1l, gateH,
                nullptr, nullptr, nullptr, nullptr, nullptr, nullptr, nullptr);
        else
            mma_gemm<false,false,true,false,false,true><<<dim3(2, MT), GT, GEMM_SMEM>>>(
                Asrc, Wmh + b * DDIM * DDIM, Wml + b * DDIM * DDIM, nullptr, Z,
                N_NODES, DDIM, DDIM, wg1h, wg1l, gateH,
                nullptr, nullptr, nullptr, nullptr, nullptr, nullptr, astats);
        gather_kernel<<<(NBUCKET * 32 + 255) / 256, 256>>>(off, ecol, Z, Mb);
        mma_gemm<false,false,false,true,true,false><<<dim3(1, MTG), GT, GEMM_SMEM>>>(
            Mb, wg1h + DDIM * GATEH, wg1l + DDIM * GATEH, nullptr, scores,
            N_NODES * K_REL, DDIM, GATEH,
            nullptr, nullptr, nullptr,
            gateH, logdeg, Wg1[b] + 2 * DDIM * GATEH, bg1[b], Wg2[b], bg2[b], nullptr);
        if (b == 0)
            fused_kernel<false><<<FUSEB, DDIM>>>(
                Mb, scores, mask, H, nullptr, Xres, colsum,
                out + N_NODES, done, stats);
        else
            fused_kernel<true><<<FUSEB, DDIM>>>(
                Mb, scores, mask, Xres, stats, Xres, colsum + SSTRIDE,
                out + N_NODES + (size_t)N_NODES * K_REL, done + 1, stats + SSTRIDE);
    }

    // head
    mma_gemm<false,false,false,true,false,true><<<dim3(1, MT), GT, GEMM_SMEM>>>(
        Xres, Wh1h, Wh1l, nullptr, out, N_NODES, DDIM, DDIM,
        nullptr, nullptr, nullptr,
        nullptr, nullptr, nullptr, bh1, Wh2, bh2, stats + SSTRIDE);
}